// round 1
// baseline (speedup 1.0000x reference)
#include <cuda_runtime.h>
#include <cstdint>

// Problem constants (fixed shapes per reference)
#define NNODES 50000
#define NEDGES 800000
#define FIN 256
#define FOUT 256
#define HEADS 8
#define CH 32
#define NEG_SLOPE 0.2f
#define LN_EPS 1e-5f

// ---------------- scratch (static device globals; no allocs allowed) -----------
__device__ float    g_h[(size_t)NNODES * FOUT];      // 51.2 MB
__device__ float    g_asrc[NNODES * HEADS];
__device__ float    g_adst[NNODES * HEADS];
__device__ unsigned g_emax[NNODES * HEADS];          // order-encoded float max
__device__ float    g_denom[NNODES * HEADS];
__device__ int      g_is64;

// Order-preserving float<->uint encode for atomicMax on signed floats
__device__ __forceinline__ unsigned enc_f(float f) {
    unsigned u = __float_as_uint(f);
    return (u & 0x80000000u) ? ~u : (u | 0x80000000u);
}
__device__ __forceinline__ float dec_f(unsigned u) {
    return (u & 0x80000000u) ? __uint_as_float(u & 0x7fffffffu)
                             : __uint_as_float(~u);
}
__device__ __forceinline__ float leaky(float v) {
    return v > 0.f ? v : NEG_SLOPE * v;
}

// ---------------- int64/int32 edge-index detection ----------------------------
__global__ void detect_idx_kernel(const long long* __restrict__ ei, int n, int cnt) {
    if (threadIdx.x == 0 && blockIdx.x == 0) {
        int ok = 1;
        for (int i = 0; i < cnt; ++i) {
            long long v = ei[i];
            if (v < 0 || v >= (long long)n) { ok = 0; break; }
        }
        g_is64 = ok;
    }
}

__device__ __forceinline__ void load_edge(const void* eidx, int e, int i,
                                          int& src, int& dst) {
    if (g_is64) {
        const long long* p = (const long long*)eidx;
        src = (int)p[i];
        dst = (int)p[(size_t)e + i];
    } else {
        const int* p = (const int*)eidx;
        src = p[i];
        dst = p[e + i];
    }
}

// ---------------- K1: tiled SGEMM h = x @ W  (M x 256 @ 256 x 256) -------------
// BM=BN=64, BK=16, 256 threads, 4x4 microtile
__global__ void gemm_kernel(const float* __restrict__ A,
                            const float* __restrict__ B,
                            float* __restrict__ C, int M) {
    __shared__ float  As[64][17];
    __shared__ float4 Bs4[16][16];   // [k][col/4]

    const int t = threadIdx.x;
    const int ty = t >> 4;           // 0..15
    const int tx = t & 15;           // 0..15
    const int rowBase = blockIdx.x * 64;
    const int colBase = blockIdx.y * 64;

    const int arow = t >> 2;         // 0..63
    const int acg  = t & 3;          // 0..3 (float4 group along K)

    float acc[4][4];
#pragma unroll
    for (int m = 0; m < 4; ++m)
#pragma unroll
        for (int n = 0; n < 4; ++n) acc[m][n] = 0.f;

    for (int k0 = 0; k0 < FIN; k0 += 16) {
        // load A tile 64x16
        float4 av = make_float4(0.f, 0.f, 0.f, 0.f);
        int gr = rowBase + arow;
        if (gr < M)
            av = *(const float4*)(A + (size_t)gr * FIN + k0 + acg * 4);
        As[arow][acg * 4 + 0] = av.x;
        As[arow][acg * 4 + 1] = av.y;
        As[arow][acg * 4 + 2] = av.z;
        As[arow][acg * 4 + 3] = av.w;
        // load B tile 16x64
        Bs4[ty][tx] = *(const float4*)(B + (size_t)(k0 + ty) * FOUT + colBase + tx * 4);
        __syncthreads();

#pragma unroll
        for (int kk = 0; kk < 16; ++kk) {
            float a0 = As[ty * 4 + 0][kk];
            float a1 = As[ty * 4 + 1][kk];
            float a2 = As[ty * 4 + 2][kk];
            float a3 = As[ty * 4 + 3][kk];
            float4 b = Bs4[kk][tx];
            acc[0][0] += a0 * b.x; acc[0][1] += a0 * b.y; acc[0][2] += a0 * b.z; acc[0][3] += a0 * b.w;
            acc[1][0] += a1 * b.x; acc[1][1] += a1 * b.y; acc[1][2] += a1 * b.z; acc[1][3] += a1 * b.w;
            acc[2][0] += a2 * b.x; acc[2][1] += a2 * b.y; acc[2][2] += a2 * b.z; acc[2][3] += a2 * b.w;
            acc[3][0] += a3 * b.x; acc[3][1] += a3 * b.y; acc[3][2] += a3 * b.z; acc[3][3] += a3 * b.w;
        }
        __syncthreads();
    }

#pragma unroll
    for (int m = 0; m < 4; ++m) {
        int gr = rowBase + ty * 4 + m;
        if (gr < M) {
            float4 v = make_float4(acc[m][0], acc[m][1], acc[m][2], acc[m][3]);
            *(float4*)(C + (size_t)gr * FOUT + colBase + tx * 4) = v;
        }
    }
}

// ---------------- K2: per-node attention logits + emax init (self loop) -------
__global__ void node_att_kernel(const float* __restrict__ att_src,
                                const float* __restrict__ att_dst, int n) {
    int gw = (blockIdx.x * blockDim.x + threadIdx.x) >> 5;
    int lane = threadIdx.x & 31;
    if (gw >= n) return;
    const float* hr = g_h + (size_t)gw * FOUT;
    float s[HEADS], d[HEADS];
#pragma unroll
    for (int k = 0; k < HEADS; ++k) {
        float hv = hr[k * CH + lane];
        s[k] = hv * att_src[k * CH + lane];
        d[k] = hv * att_dst[k * CH + lane];
    }
#pragma unroll
    for (int o = 16; o; o >>= 1) {
#pragma unroll
        for (int k = 0; k < HEADS; ++k) {
            s[k] += __shfl_down_sync(0xffffffffu, s[k], o);
            d[k] += __shfl_down_sync(0xffffffffu, d[k], o);
        }
    }
    if (lane == 0) {
#pragma unroll
        for (int k = 0; k < HEADS; ++k) {
            g_asrc[gw * HEADS + k] = s[k];
            g_adst[gw * HEADS + k] = d[k];
            // self-loop is always present: init running max with its logit
            g_emax[gw * HEADS + k] = enc_f(leaky(s[k] + d[k]));
        }
    }
}

// ---------------- K3: edge pass — segment max (encoded atomicMax) --------------
__global__ void edge_max_kernel(const void* __restrict__ eidx, int e) {
    int i = blockIdx.x * blockDim.x + threadIdx.x;
    if (i >= e) return;
    int src, dst;
    load_edge(eidx, e, i, src, dst);
    const float4* as = (const float4*)(g_asrc + src * HEADS);
    const float4* ad = (const float4*)(g_adst + dst * HEADS);
    float4 s0 = as[0], s1 = as[1];
    float4 d0 = ad[0], d1 = ad[1];
    unsigned* em = g_emax + dst * HEADS;
    atomicMax(em + 0, enc_f(leaky(s0.x + d0.x)));
    atomicMax(em + 1, enc_f(leaky(s0.y + d0.y)));
    atomicMax(em + 2, enc_f(leaky(s0.z + d0.z)));
    atomicMax(em + 3, enc_f(leaky(s0.w + d0.w)));
    atomicMax(em + 4, enc_f(leaky(s1.x + d1.x)));
    atomicMax(em + 5, enc_f(leaky(s1.y + d1.y)));
    atomicMax(em + 6, enc_f(leaky(s1.z + d1.z)));
    atomicMax(em + 7, enc_f(leaky(s1.w + d1.w)));
}

// ---------------- K4: per-(node,head) denom init with self-loop ---------------
__global__ void denom_init_kernel(int n) {
    int i = blockIdx.x * blockDim.x + threadIdx.x;
    if (i >= n * HEADS) return;
    float es = leaky(g_asrc[i] + g_adst[i]);
    float m = dec_f(g_emax[i]);
    g_denom[i] = __expf(es - m);
}

// ---------------- K5: edge pass — denom accumulate ----------------------------
__global__ void edge_denom_kernel(const void* __restrict__ eidx, int e) {
    int i = blockIdx.x * blockDim.x + threadIdx.x;
    if (i >= e) return;
    int src, dst;
    load_edge(eidx, e, i, src, dst);
    const float4* as = (const float4*)(g_asrc + src * HEADS);
    const float4* ad = (const float4*)(g_adst + dst * HEADS);
    float4 s0 = as[0], s1 = as[1];
    float4 d0 = ad[0], d1 = ad[1];
    const uint4* emv = (const uint4*)(g_emax + dst * HEADS);
    uint4 m0 = emv[0], m1 = emv[1];
    float* dn = g_denom + dst * HEADS;
    atomicAdd(dn + 0, __expf(leaky(s0.x + d0.x) - dec_f(m0.x)));
    atomicAdd(dn + 1, __expf(leaky(s0.y + d0.y) - dec_f(m0.y)));
    atomicAdd(dn + 2, __expf(leaky(s0.z + d0.z) - dec_f(m0.z)));
    atomicAdd(dn + 3, __expf(leaky(s0.w + d0.w) - dec_f(m0.w)));
    atomicAdd(dn + 4, __expf(leaky(s1.x + d1.x) - dec_f(m1.x)));
    atomicAdd(dn + 5, __expf(leaky(s1.y + d1.y) - dec_f(m1.y)));
    atomicAdd(dn + 6, __expf(leaky(s1.z + d1.z) - dec_f(m1.z)));
    atomicAdd(dn + 7, __expf(leaky(s1.w + d1.w) - dec_f(m1.w)));
}

// ---------------- K6: out init with self-loop contribution --------------------
__global__ void out_init_kernel(float* __restrict__ out, int n) {
    int i = blockIdx.x * blockDim.x + threadIdx.x;
    if (i >= n * FOUT) return;
    int node = i >> 8;
    int c = i & 255;
    int k = c >> 5;
    int nk = node * HEADS + k;
    float es = leaky(g_asrc[nk] + g_adst[nk]);
    float m = dec_f(g_emax[nk]);
    float alpha = __expf(es - m) / g_denom[nk];
    out[i] = g_h[i] * alpha;
}

// ---------------- K7: edge scatter — out[dst] += h[src] * alpha ---------------
// one warp per edge; lane handles 8 consecutive columns (all in one head)
__global__ void edge_scatter_kernel(const void* __restrict__ eidx,
                                    float* __restrict__ out, int e) {
    int gw = (blockIdx.x * blockDim.x + threadIdx.x) >> 5;
    int lane = threadIdx.x & 31;
    if (gw >= e) return;
    int src, dst;
    load_edge(eidx, e, gw, src, dst);

    float alpha = 0.f;
    if (lane < HEADS) {
        int nk = dst * HEADS + lane;
        float es = leaky(g_asrc[src * HEADS + lane] + g_adst[nk]);
        float m = dec_f(g_emax[nk]);
        alpha = __expf(es - m) / g_denom[nk];
    }
    // lane's 8 columns [lane*8, lane*8+8) all belong to head lane/4
    float amy = __shfl_sync(0xffffffffu, alpha, lane >> 2);

    const float4* hs = (const float4*)(g_h + (size_t)src * FOUT) + lane * 2;
    float4 v0 = hs[0], v1 = hs[1];
    float* ob = out + (size_t)dst * FOUT + lane * 8;
    atomicAdd(ob + 0, v0.x * amy);
    atomicAdd(ob + 1, v0.y * amy);
    atomicAdd(ob + 2, v0.z * amy);
    atomicAdd(ob + 3, v0.w * amy);
    atomicAdd(ob + 4, v1.x * amy);
    atomicAdd(ob + 5, v1.y * amy);
    atomicAdd(ob + 6, v1.z * amy);
    atomicAdd(ob + 7, v1.w * amy);
}

// ---------------- K8: bias + LayerNorm + ReLU (in place on out) ---------------
__global__ void ln_relu_kernel(float* __restrict__ out,
                               const float* __restrict__ bias,
                               const float* __restrict__ gamma,
                               const float* __restrict__ beta, int n) {
    int gw = (blockIdx.x * blockDim.x + threadIdx.x) >> 5;
    int lane = threadIdx.x & 31;
    if (gw >= n) return;
    float* row = out + (size_t)gw * FOUT;
    int c0 = lane * 8;
    float4 v0 = *(const float4*)(row + c0);
    float4 v1 = *(const float4*)(row + c0 + 4);
    float4 b0 = *(const float4*)(bias + c0);
    float4 b1 = *(const float4*)(bias + c0 + 4);
    v0.x += b0.x; v0.y += b0.y; v0.z += b0.z; v0.w += b0.w;
    v1.x += b1.x; v1.y += b1.y; v1.z += b1.z; v1.w += b1.w;

    float s = v0.x + v0.y + v0.z + v0.w + v1.x + v1.y + v1.z + v1.w;
    float q = v0.x * v0.x + v0.y * v0.y + v0.z * v0.z + v0.w * v0.w +
              v1.x * v1.x + v1.y * v1.y + v1.z * v1.z + v1.w * v1.w;
#pragma unroll
    for (int o = 16; o; o >>= 1) {
        s += __shfl_xor_sync(0xffffffffu, s, o);
        q += __shfl_xor_sync(0xffffffffu, q, o);
    }
    float mu = s * (1.f / FOUT);
    float var = q * (1.f / FOUT) - mu * mu;
    float rs = rsqrtf(var + LN_EPS);

    float4 g0 = *(const float4*)(gamma + c0);
    float4 g1 = *(const float4*)(gamma + c0 + 4);
    float4 e0 = *(const float4*)(beta + c0);
    float4 e1 = *(const float4*)(beta + c0 + 4);
    float4 r0, r1;
    r0.x = fmaxf((v0.x - mu) * rs * g0.x + e0.x, 0.f);
    r0.y = fmaxf((v0.y - mu) * rs * g0.y + e0.y, 0.f);
    r0.z = fmaxf((v0.z - mu) * rs * g0.z + e0.z, 0.f);
    r0.w = fmaxf((v0.w - mu) * rs * g0.w + e0.w, 0.f);
    r1.x = fmaxf((v1.x - mu) * rs * g1.x + e1.x, 0.f);
    r1.y = fmaxf((v1.y - mu) * rs * g1.y + e1.y, 0.f);
    r1.z = fmaxf((v1.z - mu) * rs * g1.z + e1.z, 0.f);
    r1.w = fmaxf((v1.w - mu) * rs * g1.w + e1.w, 0.f);
    *(float4*)(row + c0) = r0;
    *(float4*)(row + c0 + 4) = r1;
}

// ---------------- launch ------------------------------------------------------
extern "C" void kernel_launch(void* const* d_in, const int* in_sizes, int n_in,
                              void* d_out, int out_size) {
    const float* x       = (const float*)d_in[0];
    const void*  eidx    = d_in[1];
    const float* W       = (const float*)d_in[2];
    const float* att_src = (const float*)d_in[3];
    const float* att_dst = (const float*)d_in[4];
    const float* bias    = (const float*)d_in[5];
    const float* gamma   = (const float*)d_in[6];
    const float* beta    = (const float*)d_in[7];
    float* out = (float*)d_out;

    const int n = in_sizes[0] / FIN;     // 50000
    const int e = in_sizes[1] / 2;       // 800000

    // detect int64 vs int32 edge_index
    int cnt = 64 < 2 * e ? 64 : 2 * e;
    detect_idx_kernel<<<1, 32>>>((const long long*)eidx, n, cnt);

    float* hptr;
    cudaGetSymbolAddress((void**)&hptr, g_h);

    dim3 ggrid((n + 63) / 64, FOUT / 64);
    gemm_kernel<<<ggrid, 256>>>(x, W, hptr, n);

    node_att_kernel<<<(n * 32 + 255) / 256, 256>>>(att_src, att_dst, n);
    edge_max_kernel<<<(e + 255) / 256, 256>>>(eidx, e);
    denom_init_kernel<<<(n * HEADS + 255) / 256, 256>>>(n);
    edge_denom_kernel<<<(e + 255) / 256, 256>>>(eidx, e);
    out_init_kernel<<<(n * FOUT + 255) / 256, 256>>>(out, n);
    edge_scatter_kernel<<<(e * 32 + 255) / 256, 256>>>(eidx, out, e);
    ln_relu_kernel<<<(n * 32 + 255) / 256, 256>>>(out, bias, gamma, beta, n);
}

// round 2
// speedup vs baseline: 3.2392x; 3.2392x over previous
#include <cuda_runtime.h>
#include <cstdint>

#define NNODES 50000
#define NEDGES 800000
#define FIN 256
#define FOUT 256
#define HEADS 8
#define CH 32
#define NEG_SLOPE 0.2f
#define LN_EPS 1e-5f

// ---------------- scratch (static device globals) -----------------------------
__device__ float g_h[(size_t)NNODES * FOUT];   // 51.2 MB
__device__ float g_asrc[NNODES * HEADS];
__device__ float g_adst[NNODES * HEADS];
__device__ int   g_cnt[NNODES];
__device__ int   g_off[NNODES + 1];
__device__ int   g_cur[NNODES];
__device__ int   g_col[NEDGES];                // src per edge, grouped by dst
__device__ int   g_is64;

__device__ __forceinline__ float leaky(float v) {
    return v > 0.f ? v : NEG_SLOPE * v;
}

// ---------------- int64/int32 edge-index detection ----------------------------
__global__ void detect_idx_kernel(const long long* __restrict__ ei, int n, int cnt) {
    if (threadIdx.x == 0 && blockIdx.x == 0) {
        int ok = 1;
        for (int i = 0; i < cnt; ++i) {
            long long v = ei[i];
            if (v < 0 || v >= (long long)n) { ok = 0; break; }
        }
        g_is64 = ok;
    }
}

__device__ __forceinline__ void load_edge(const void* eidx, int e, int i,
                                          int& src, int& dst) {
    if (g_is64) {
        const long long* p = (const long long*)eidx;
        src = (int)p[i];
        dst = (int)p[(size_t)e + i];
    } else {
        const int* p = (const int*)eidx;
        src = p[i];
        dst = p[e + i];
    }
}

// ---------------- K1: SGEMM h = x @ W (128x128x8 tiles, 8x8 microtile) --------
__global__ __launch_bounds__(256) void gemm_kernel(const float* __restrict__ A,
                                                   const float* __restrict__ B,
                                                   float* __restrict__ C, int M) {
    __shared__ float As[8][132];
    __shared__ float Bs[8][128];

    const int t = threadIdx.x;
    const int tx = t & 15;            // 0..15 -> col microtile
    const int ty = t >> 4;            // 0..15 -> row microtile
    const int rowBase = blockIdx.x * 128;
    const int colBase = blockIdx.y * 128;

    const int arow = t >> 1;          // 0..127
    const int acol = (t & 1) << 2;    // 0 or 4
    const int brow = t >> 5;          // 0..7
    const int bcol = (t & 31) << 2;   // 0..124

    float acc[8][8];
#pragma unroll
    for (int i = 0; i < 8; ++i)
#pragma unroll
        for (int j = 0; j < 8; ++j) acc[i][j] = 0.f;

    for (int k0 = 0; k0 < FIN; k0 += 8) {
        float4 av = make_float4(0.f, 0.f, 0.f, 0.f);
        int gr = rowBase + arow;
        if (gr < M) av = *(const float4*)(A + (size_t)gr * FIN + k0 + acol);
        As[acol + 0][arow] = av.x;
        As[acol + 1][arow] = av.y;
        As[acol + 2][arow] = av.z;
        As[acol + 3][arow] = av.w;
        float4 bv = *(const float4*)(B + (size_t)(k0 + brow) * FOUT + colBase + bcol);
        *(float4*)&Bs[brow][bcol] = bv;
        __syncthreads();

#pragma unroll
        for (int kk = 0; kk < 8; ++kk) {
            float4 a0 = *(float4*)&As[kk][ty * 8];
            float4 a1 = *(float4*)&As[kk][ty * 8 + 4];
            float4 b0 = *(float4*)&Bs[kk][tx * 8];
            float4 b1 = *(float4*)&Bs[kk][tx * 8 + 4];
            float a[8] = {a0.x, a0.y, a0.z, a0.w, a1.x, a1.y, a1.z, a1.w};
            float b[8] = {b0.x, b0.y, b0.z, b0.w, b1.x, b1.y, b1.z, b1.w};
#pragma unroll
            for (int i = 0; i < 8; ++i)
#pragma unroll
                for (int j = 0; j < 8; ++j) acc[i][j] += a[i] * b[j];
        }
        __syncthreads();
    }

#pragma unroll
    for (int i = 0; i < 8; ++i) {
        int gr = rowBase + ty * 8 + i;
        if (gr < M) {
            float* cp = C + (size_t)gr * FOUT + colBase + tx * 8;
            *(float4*)cp       = make_float4(acc[i][0], acc[i][1], acc[i][2], acc[i][3]);
            *(float4*)(cp + 4) = make_float4(acc[i][4], acc[i][5], acc[i][6], acc[i][7]);
        }
    }
}

// ---------------- K2: per-node attention logits -------------------------------
__global__ void node_att_kernel(const float* __restrict__ att_src,
                                const float* __restrict__ att_dst, int n) {
    int gw = (blockIdx.x * blockDim.x + threadIdx.x) >> 5;
    int lane = threadIdx.x & 31;
    if (gw >= n) return;
    const float* hr = g_h + (size_t)gw * FOUT;
    float s[HEADS], d[HEADS];
#pragma unroll
    for (int k = 0; k < HEADS; ++k) {
        float hv = hr[k * CH + lane];
        s[k] = hv * att_src[k * CH + lane];
        d[k] = hv * att_dst[k * CH + lane];
    }
#pragma unroll
    for (int o = 16; o; o >>= 1) {
#pragma unroll
        for (int k = 0; k < HEADS; ++k) {
            s[k] += __shfl_down_sync(0xffffffffu, s[k], o);
            d[k] += __shfl_down_sync(0xffffffffu, d[k], o);
        }
    }
    if (lane == 0) {
#pragma unroll
        for (int k = 0; k < HEADS; ++k) {
            g_asrc[gw * HEADS + k] = s[k];
            g_adst[gw * HEADS + k] = d[k];
        }
    }
}

// ---------------- CSR build ----------------------------------------------------
__global__ void zero_cnt_kernel(int n) {
    int i = blockIdx.x * blockDim.x + threadIdx.x;
    if (i < n) g_cnt[i] = 0;
}

__global__ void count_kernel(const void* __restrict__ eidx, int e) {
    int i = blockIdx.x * blockDim.x + threadIdx.x;
    if (i >= e) return;
    int src, dst;
    load_edge(eidx, e, i, src, dst);
    atomicAdd(&g_cnt[dst], 1);
}

__global__ __launch_bounds__(1024) void scan_kernel(int n) {
    __shared__ int sh[1024];
    int t = threadIdx.x;
    int per = (n + 1023) >> 10;
    int s0 = t * per;
    int s1 = s0 + per < n ? s0 + per : n;
    int sum = 0;
    for (int i = s0; i < s1; ++i) sum += g_cnt[i];
    sh[t] = sum;
    __syncthreads();
    for (int o = 1; o < 1024; o <<= 1) {
        int v = (t >= o) ? sh[t - o] : 0;
        __syncthreads();
        sh[t] += v;
        __syncthreads();
    }
    int run = (t == 0) ? 0 : sh[t - 1];
    for (int i = s0; i < s1; ++i) {
        g_off[i] = run;
        g_cur[i] = run;
        run += g_cnt[i];
    }
    if (t == 1023) g_off[n] = sh[1023];
}

__global__ void fill_kernel(const void* __restrict__ eidx, int e) {
    int i = blockIdx.x * blockDim.x + threadIdx.x;
    if (i >= e) return;
    int src, dst;
    load_edge(eidx, e, i, src, dst);
    int pos = atomicAdd(&g_cur[dst], 1);
    g_col[pos] = src;
}

// ---------------- K7: fused softmax + aggregate + bias + LN + ReLU ------------
// one warp per dst node; output row written exactly once, no atomics
__global__ __launch_bounds__(256) void aggregate_kernel(float* __restrict__ out,
                                                        const float* __restrict__ bias,
                                                        const float* __restrict__ gamma,
                                                        const float* __restrict__ beta,
                                                        int n) {
    int d = (blockIdx.x * blockDim.x + threadIdx.x) >> 5;
    int lane = threadIdx.x & 31;
    if (d >= n) return;

    const int off = g_off[d];
    const int deg = g_off[d + 1] - off;

    float4 t0 = *(const float4*)(g_adst + d * HEADS);
    float4 t1 = *(const float4*)(g_adst + d * HEADS + 4);
    float adst8[8] = {t0.x, t0.y, t0.z, t0.w, t1.x, t1.y, t1.z, t1.w};
    float4 u0 = *(const float4*)(g_asrc + d * HEADS);
    float4 u1 = *(const float4*)(g_asrc + d * HEADS + 4);
    float asd[8] = {u0.x, u0.y, u0.z, u0.w, u1.x, u1.y, u1.z, u1.w};

    // ---- pass A1: per-head max (self-loop seeds the max) ----
    float m[8];
#pragma unroll
    for (int k = 0; k < 8; ++k) m[k] = leaky(asd[k] + adst8[k]);

    for (int i = lane; i < deg; i += 32) {
        int s = __ldg(g_col + off + i);
        float4 a0 = *(const float4*)(g_asrc + s * HEADS);
        float4 a1 = *(const float4*)(g_asrc + s * HEADS + 4);
        m[0] = fmaxf(m[0], leaky(a0.x + adst8[0]));
        m[1] = fmaxf(m[1], leaky(a0.y + adst8[1]));
        m[2] = fmaxf(m[2], leaky(a0.z + adst8[2]));
        m[3] = fmaxf(m[3], leaky(a0.w + adst8[3]));
        m[4] = fmaxf(m[4], leaky(a1.x + adst8[4]));
        m[5] = fmaxf(m[5], leaky(a1.y + adst8[5]));
        m[6] = fmaxf(m[6], leaky(a1.z + adst8[6]));
        m[7] = fmaxf(m[7], leaky(a1.w + adst8[7]));
    }
#pragma unroll
    for (int o = 16; o; o >>= 1)
#pragma unroll
        for (int k = 0; k < 8; ++k)
            m[k] = fmaxf(m[k], __shfl_xor_sync(0xffffffffu, m[k], o));

    // ---- pass A2: per-head denom ----
    float sm[8] = {0.f, 0.f, 0.f, 0.f, 0.f, 0.f, 0.f, 0.f};
    for (int i = lane; i < deg; i += 32) {
        int s = __ldg(g_col + off + i);
        float4 a0 = *(const float4*)(g_asrc + s * HEADS);
        float4 a1 = *(const float4*)(g_asrc + s * HEADS + 4);
        sm[0] += __expf(leaky(a0.x + adst8[0]) - m[0]);
        sm[1] += __expf(leaky(a0.y + adst8[1]) - m[1]);
        sm[2] += __expf(leaky(a0.z + adst8[2]) - m[2]);
        sm[3] += __expf(leaky(a0.w + adst8[3]) - m[3]);
        sm[4] += __expf(leaky(a1.x + adst8[4]) - m[4]);
        sm[5] += __expf(leaky(a1.y + adst8[5]) - m[5]);
        sm[6] += __expf(leaky(a1.z + adst8[6]) - m[6]);
        sm[7] += __expf(leaky(a1.w + adst8[7]) - m[7]);
    }
#pragma unroll
    for (int o = 16; o; o >>= 1)
#pragma unroll
        for (int k = 0; k < 8; ++k)
            sm[k] += __shfl_xor_sync(0xffffffffu, sm[k], o);
#pragma unroll
    for (int k = 0; k < 8; ++k)
        sm[k] += __expf(leaky(asd[k] + adst8[k]) - m[k]);   // self-loop term

    // per-lane head parameters (avoid dynamic register indexing)
    const int lk = lane & 7;        // head this lane evaluates alphas for
    const int myhead = lane >> 2;   // head owning this lane's 8 output channels
    float m_lk = 0.f, inv_lk = 0.f, adst_lk = 0.f;
    float m_h = 0.f, inv_h = 0.f, adst_h = 0.f, asd_h = 0.f;
#pragma unroll
    for (int k = 0; k < 8; ++k) {
        float invk = 1.f / sm[k];
        if (lk == k)     { m_lk = m[k]; inv_lk = invk; adst_lk = adst8[k]; }
        if (myhead == k) { m_h = m[k]; inv_h = invk; adst_h = adst8[k]; asd_h = asd[k]; }
    }

    // ---- pass B: gather-accumulate (init with self-loop contribution) ----
    float sa = __expf(leaky(asd_h + adst_h) - m_h) * inv_h;
    const float4* hd = (const float4*)(g_h + (size_t)d * FOUT) + lane * 2;
    float4 v0 = hd[0], v1 = hd[1];
    float4 acc0 = make_float4(v0.x * sa, v0.y * sa, v0.z * sa, v0.w * sa);
    float4 acc1 = make_float4(v1.x * sa, v1.y * sa, v1.z * sa, v1.w * sa);

    for (int j = 0; j < deg; ++j) {
        int s = __ldg(g_col + off + j);                 // warp-uniform
        float a = __ldg(g_asrc + s * HEADS + lk);
        float al = __expf(leaky(a + adst_lk) - m_lk) * inv_lk;
        float av = __shfl_sync(0xffffffffu, al, myhead);
        const float4* hs = (const float4*)(g_h + (size_t)s * FOUT) + lane * 2;
        float4 w0 = hs[0], w1 = hs[1];
        acc0.x += w0.x * av; acc0.y += w0.y * av;
        acc0.z += w0.z * av; acc0.w += w0.w * av;
        acc1.x += w1.x * av; acc1.y += w1.y * av;
        acc1.z += w1.z * av; acc1.w += w1.w * av;
    }

    // ---- bias + LayerNorm + ReLU ----
    const int c0 = lane * 8;
    float4 b0 = *(const float4*)(bias + c0);
    float4 b1 = *(const float4*)(bias + c0 + 4);
    acc0.x += b0.x; acc0.y += b0.y; acc0.z += b0.z; acc0.w += b0.w;
    acc1.x += b1.x; acc1.y += b1.y; acc1.z += b1.z; acc1.w += b1.w;

    float s = acc0.x + acc0.y + acc0.z + acc0.w + acc1.x + acc1.y + acc1.z + acc1.w;
    float q = acc0.x * acc0.x + acc0.y * acc0.y + acc0.z * acc0.z + acc0.w * acc0.w +
              acc1.x * acc1.x + acc1.y * acc1.y + acc1.z * acc1.z + acc1.w * acc1.w;
#pragma unroll
    for (int o = 16; o; o >>= 1) {
        s += __shfl_xor_sync(0xffffffffu, s, o);
        q += __shfl_xor_sync(0xffffffffu, q, o);
    }
    float mu = s * (1.f / FOUT);
    float var = q * (1.f / FOUT) - mu * mu;
    float rs = rsqrtf(var + LN_EPS);

    float4 g0 = *(const float4*)(gamma + c0);
    float4 g1 = *(const float4*)(gamma + c0 + 4);
    float4 e0 = *(const float4*)(beta + c0);
    float4 e1 = *(const float4*)(beta + c0 + 4);
    float4 r0, r1;
    r0.x = fmaxf((acc0.x - mu) * rs * g0.x + e0.x, 0.f);
    r0.y = fmaxf((acc0.y - mu) * rs * g0.y + e0.y, 0.f);
    r0.z = fmaxf((acc0.z - mu) * rs * g0.z + e0.z, 0.f);
    r0.w = fmaxf((acc0.w - mu) * rs * g0.w + e0.w, 0.f);
    r1.x = fmaxf((acc1.x - mu) * rs * g1.x + e1.x, 0.f);
    r1.y = fmaxf((acc1.y - mu) * rs * g1.y + e1.y, 0.f);
    r1.z = fmaxf((acc1.z - mu) * rs * g1.z + e1.z, 0.f);
    r1.w = fmaxf((acc1.w - mu) * rs * g1.w + e1.w, 0.f);
    float* row = out + (size_t)d * FOUT + c0;
    *(float4*)row       = r0;
    *(float4*)(row + 4) = r1;
}

// ---------------- launch ------------------------------------------------------
extern "C" void kernel_launch(void* const* d_in, const int* in_sizes, int n_in,
                              void* d_out, int out_size) {
    const float* x       = (const float*)d_in[0];
    const void*  eidx    = d_in[1];
    const float* W       = (const float*)d_in[2];
    const float* att_src = (const float*)d_in[3];
    const float* att_dst = (const float*)d_in[4];
    const float* bias    = (const float*)d_in[5];
    const float* gamma   = (const float*)d_in[6];
    const float* beta    = (const float*)d_in[7];
    float* out = (float*)d_out;

    const int n = in_sizes[0] / FIN;     // 50000
    const int e = in_sizes[1] / 2;       // 800000

    int cnt = 64 < 2 * e ? 64 : 2 * e;
    detect_idx_kernel<<<1, 32>>>((const long long*)eidx, n, cnt);

    float* hptr;
    cudaGetSymbolAddress((void**)&hptr, g_h);

    dim3 ggrid((n + 127) / 128, FOUT / 128);
    gemm_kernel<<<ggrid, 256>>>(x, W, hptr, n);

    node_att_kernel<<<(n * 32 + 255) / 256, 256>>>(att_src, att_dst, n);

    zero_cnt_kernel<<<(n + 255) / 256, 256>>>(n);
    count_kernel<<<(e + 255) / 256, 256>>>(eidx, e);
    scan_kernel<<<1, 1024>>>(n);
    fill_kernel<<<(e + 255) / 256, 256>>>(eidx, e);

    aggregate_kernel<<<(n * 32 + 255) / 256, 256>>>(out, bias, gamma, beta, n);
}

// round 7
// speedup vs baseline: 4.8875x; 1.5089x over previous
#include <cuda_runtime.h>
#include <cuda_bf16.h>
#include <cstdint>

#define NNODES 50000
#define NEDGES 800000
#define FIN 256
#define FOUT 256
#define HEADS 8
#define CH 32
#define NEG_SLOPE 0.2f
#define LN_EPS 1e-5f

// ---------------- scratch (static device globals) -----------------------------
__device__ float g_h[(size_t)NNODES * FOUT];           // 51.2 MB
__device__ __nv_bfloat16 g_xh[(size_t)NNODES * FIN];   // 25.6 MB
__device__ __nv_bfloat16 g_xl[(size_t)NNODES * FIN];   // 25.6 MB
__device__ __nv_bfloat16 g_wh[FOUT * FIN];             // Wt hi: [n][k]
__device__ __nv_bfloat16 g_wl[FOUT * FIN];             // Wt lo: [n][k]
__device__ float g_asrc[NNODES * HEADS];
__device__ float g_adst[NNODES * HEADS];
__device__ int   g_cnt[NNODES];
__device__ int   g_off[NNODES + 1];
__device__ int   g_cur[NNODES];
__device__ int   g_col[NEDGES];
__device__ int   g_bsum[256];
__device__ int   g_is64;

__device__ __forceinline__ float leaky(float v) {
    return v > 0.f ? v : NEG_SLOPE * v;
}

__device__ __forceinline__ uint32_t smem_u32(const void* p) {
    uint32_t a;
    asm("{ .reg .u64 t; cvta.to.shared.u64 t, %1; cvt.u32.u64 %0, t; }"
        : "=r"(a) : "l"(p));
    return a;
}

// ---------------- int64/int32 edge-index detection ----------------------------
__global__ void detect_idx_kernel(const long long* __restrict__ ei, int n, int cnt) {
    if (threadIdx.x == 0 && blockIdx.x == 0) {
        int ok = 1;
        for (int i = 0; i < cnt; ++i) {
            long long v = ei[i];
            if (v < 0 || v >= (long long)n) { ok = 0; break; }
        }
        g_is64 = ok;
    }
}

__device__ __forceinline__ void load_edge(const void* eidx, int e, int i,
                                          int& src, int& dst) {
    if (g_is64) {
        const long long* p = (const long long*)eidx;
        src = (int)p[i];
        dst = (int)p[(size_t)e + i];
    } else {
        const int* p = (const int*)eidx;
        src = p[i];
        dst = p[e + i];
    }
}

// ---------------- conversions: fp32 -> bf16 hi/lo ------------------------------
__global__ void xconv_kernel(const float* __restrict__ x, int M) {
    int i = blockIdx.x * blockDim.x + threadIdx.x;   // one float4 per thread
    if (i >= M * (FIN / 4)) return;
    float4 v = *(const float4*)(x + (size_t)i * 4);
    __nv_bfloat16 h0 = __float2bfloat16(v.x);
    __nv_bfloat16 h1 = __float2bfloat16(v.y);
    __nv_bfloat16 h2 = __float2bfloat16(v.z);
    __nv_bfloat16 h3 = __float2bfloat16(v.w);
    __nv_bfloat16 l0 = __float2bfloat16(v.x - __bfloat162float(h0));
    __nv_bfloat16 l1 = __float2bfloat16(v.y - __bfloat162float(h1));
    __nv_bfloat16 l2 = __float2bfloat16(v.z - __bfloat162float(h2));
    __nv_bfloat16 l3 = __float2bfloat16(v.w - __bfloat162float(h3));
    ushort4 hv = make_ushort4(*(unsigned short*)&h0, *(unsigned short*)&h1,
                              *(unsigned short*)&h2, *(unsigned short*)&h3);
    ushort4 lv = make_ushort4(*(unsigned short*)&l0, *(unsigned short*)&l1,
                              *(unsigned short*)&l2, *(unsigned short*)&l3);
    *(ushort4*)(g_xh + (size_t)i * 4) = hv;
    *(ushort4*)(g_xl + (size_t)i * 4) = lv;
}

__global__ void wconv_kernel(const float* __restrict__ W) {
    int idx = blockIdx.x * blockDim.x + threadIdx.x;
    if (idx >= FOUT * FIN) return;
    int n = idx >> 8;      // out channel
    int k = idx & 255;     // in channel
    float w = W[k * FOUT + n];
    __nv_bfloat16 hi = __float2bfloat16(w);
    __nv_bfloat16 lo = __float2bfloat16(w - __bfloat162float(hi));
    g_wh[n * FIN + k] = hi;   // B operand col-major (k contiguous per n)
    g_wl[n * FIN + k] = lo;
}

// ---------------- K1: bf16 mma.sync GEMM, 3-term split precision ---------------
// h = xh@Wh + xl@Wh + xh@Wl ; CTA tile 128x128, 8 warps x (64x32)
#define APITCH 40
__global__ __launch_bounds__(256) void gemm_mma_kernel(int M) {
    __shared__ __nv_bfloat16 As[128][APITCH];
    __shared__ __nv_bfloat16 Bs[128][APITCH];

    const int tid = threadIdx.x;
    const int warp = tid >> 5;
    const int lane = tid & 31;
    const int wm = warp & 1;       // 2 warp-rows (64 each)
    const int wn = warp >> 1;      // 4 warp-cols (32 each)
    const int m0 = blockIdx.x * 128;
    const int n0 = blockIdx.y * 128;

    float acc[4][4][4];
#pragma unroll
    for (int a = 0; a < 4; ++a)
#pragma unroll
        for (int b = 0; b < 4; ++b)
#pragma unroll
            for (int c = 0; c < 4; ++c) acc[a][b][c] = 0.f;

    const int lrow = tid >> 1;            // 0..127
    const int lk = (tid & 1) * 16;        // 0 or 16 (16 bf16 per thread)

    // ldmatrix smem addresses (fixed per lane, offset by ks)
    const int arow = wm * 64 + (lane & 7) + ((lane >> 3) & 1) * 8;
    const int acol = (lane >> 4) * 8;
    const int l16 = lane & 15;
    const int brow = wn * 32 + (l16 & 7);
    const int bcol = ((l16 >> 3) & 1) * 8;

    for (int p = 0; p < 3; ++p) {
        const __nv_bfloat16* Ag = (p == 1) ? g_xl : g_xh;
        const __nv_bfloat16* Bg = (p == 2) ? g_wl : g_wh;
        for (int kc = 0; kc < FIN; kc += 32) {
            // each thread owns 16 bf16 (= two uint4) of its row's K-chunk
            uint4 av0 = make_uint4(0, 0, 0, 0), av1 = av0;
            int gr = m0 + lrow;
            if (gr < M) {
                const __nv_bfloat16* ap = Ag + (size_t)gr * FIN + kc + lk;
                av0 = *(const uint4*)ap;
                av1 = *(const uint4*)(ap + 8);
            }
            *(uint4*)&As[lrow][lk]     = av0;
            *(uint4*)&As[lrow][lk + 8] = av1;
            const __nv_bfloat16* bp = Bg + (size_t)(n0 + lrow) * FIN + kc + lk;
            *(uint4*)&Bs[lrow][lk]     = *(const uint4*)bp;
            *(uint4*)&Bs[lrow][lk + 8] = *(const uint4*)(bp + 8);
            __syncthreads();

#pragma unroll
            for (int ks = 0; ks < 32; ks += 16) {
                uint32_t a[4][4];
#pragma unroll
                for (int mf = 0; mf < 4; ++mf) {
                    uint32_t ad = smem_u32(&As[arow + mf * 16][ks + acol]);
                    asm volatile(
                        "ldmatrix.sync.aligned.m8n8.x4.shared.b16 {%0,%1,%2,%3}, [%4];"
                        : "=r"(a[mf][0]), "=r"(a[mf][1]), "=r"(a[mf][2]), "=r"(a[mf][3])
                        : "r"(ad));
                }
                uint32_t b[4][2];
#pragma unroll
                for (int nf = 0; nf < 4; ++nf) {
                    uint32_t bd = smem_u32(&Bs[brow + nf * 8][ks + bcol]);
                    asm volatile(
                        "ldmatrix.sync.aligned.m8n8.x2.shared.b16 {%0,%1}, [%2];"
                        : "=r"(b[nf][0]), "=r"(b[nf][1]) : "r"(bd));
                }
#pragma unroll
                for (int mf = 0; mf < 4; ++mf)
#pragma unroll
                    for (int nf = 0; nf < 4; ++nf) {
                        asm volatile(
                            "mma.sync.aligned.m16n8k16.row.col.f32.bf16.bf16.f32 "
                            "{%0,%1,%2,%3}, {%4,%5,%6,%7}, {%8,%9}, {%0,%1,%2,%3};"
                            : "+f"(acc[mf][nf][0]), "+f"(acc[mf][nf][1]),
                              "+f"(acc[mf][nf][2]), "+f"(acc[mf][nf][3])
                            : "r"(a[mf][0]), "r"(a[mf][1]), "r"(a[mf][2]), "r"(a[mf][3]),
                              "r"(b[nf][0]), "r"(b[nf][1]));
                    }
            }
            __syncthreads();
        }
    }

    // epilogue: write h
    const int rbase = m0 + wm * 64 + (lane >> 2);
    const int cbase = n0 + wn * 32 + (lane & 3) * 2;
#pragma unroll
    for (int mf = 0; mf < 4; ++mf) {
        int r0 = rbase + mf * 16;
#pragma unroll
        for (int nf = 0; nf < 4; ++nf) {
            int c = cbase + nf * 8;
            if (r0 < M)
                *(float2*)(g_h + (size_t)r0 * FOUT + c) =
                    make_float2(acc[mf][nf][0], acc[mf][nf][1]);
            if (r0 + 8 < M)
                *(float2*)(g_h + (size_t)(r0 + 8) * FOUT + c) =
                    make_float2(acc[mf][nf][2], acc[mf][nf][3]);
        }
    }
}

// ---------------- K2: per-node attention logits -------------------------------
__global__ void node_att_kernel(const float* __restrict__ att_src,
                                const float* __restrict__ att_dst, int n) {
    int gw = (blockIdx.x * blockDim.x + threadIdx.x) >> 5;
    int lane = threadIdx.x & 31;
    if (gw >= n) return;
    const float* hr = g_h + (size_t)gw * FOUT;
    float s[HEADS], d[HEADS];
#pragma unroll
    for (int k = 0; k < HEADS; ++k) {
        float hv = hr[k * CH + lane];
        s[k] = hv * att_src[k * CH + lane];
        d[k] = hv * att_dst[k * CH + lane];
    }
#pragma unroll
    for (int o = 16; o; o >>= 1) {
#pragma unroll
        for (int k = 0; k < HEADS; ++k) {
            s[k] += __shfl_down_sync(0xffffffffu, s[k], o);
            d[k] += __shfl_down_sync(0xffffffffu, d[k], o);
        }
    }
    if (lane == 0) {
#pragma unroll
        for (int k = 0; k < HEADS; ++k) {
            g_asrc[gw * HEADS + k] = s[k];
            g_adst[gw * HEADS + k] = d[k];
        }
    }
}

// ---------------- CSR build ----------------------------------------------------
__global__ void zero_cnt_kernel(int n) {
    int i = blockIdx.x * blockDim.x + threadIdx.x;
    if (i < n) g_cnt[i] = 0;
}

__global__ void count_kernel(const void* __restrict__ eidx, int e) {
    int i = blockIdx.x * blockDim.x + threadIdx.x;
    if (i >= e) return;
    int src, dst;
    load_edge(eidx, e, i, src, dst);
    atomicAdd(&g_cnt[dst], 1);
}

__global__ __launch_bounds__(256) void scan1_kernel(int n) {
    __shared__ int sh[256];
    int i = blockIdx.x * 256 + threadIdx.x;
    sh[threadIdx.x] = (i < n) ? g_cnt[i] : 0;
    __syncthreads();
    for (int o = 128; o; o >>= 1) {
        if (threadIdx.x < o) sh[threadIdx.x] += sh[threadIdx.x + o];
        __syncthreads();
    }
    if (threadIdx.x == 0) g_bsum[blockIdx.x] = sh[0];
}

__global__ __launch_bounds__(256) void scan2_kernel(int nb, int n) {
    __shared__ int sh[256];
    int t = threadIdx.x;
    sh[t] = (t < nb) ? g_bsum[t] : 0;
    __syncthreads();
    for (int o = 1; o < 256; o <<= 1) {
        int v = (t >= o) ? sh[t - o] : 0;
        __syncthreads();
        sh[t] += v;
        __syncthreads();
    }
    if (t < nb) g_bsum[t] = sh[t];       // inclusive
    if (t == 255) g_off[n] = sh[nb - 1];
}

__global__ __launch_bounds__(256) void scan3_kernel(int n) {
    __shared__ int sh[256];
    int t = threadIdx.x;
    int i = blockIdx.x * 256 + t;
    int v = (i < n) ? g_cnt[i] : 0;
    sh[t] = v;
    __syncthreads();
    for (int o = 1; o < 256; o <<= 1) {
        int u = (t >= o) ? sh[t - o] : 0;
        __syncthreads();
        sh[t] += u;
        __syncthreads();
    }
    int bex = (blockIdx.x > 0) ? g_bsum[blockIdx.x - 1] : 0;
    if (i < n) {
        int off = bex + sh[t] - v;   // exclusive
        g_off[i] = off;
        g_cur[i] = off;
    }
}

__global__ void fill_kernel(const void* __restrict__ eidx, int e) {
    int i = blockIdx.x * blockDim.x + threadIdx.x;
    if (i >= e) return;
    int src, dst;
    load_edge(eidx, e, i, src, dst);
    int pos = atomicAdd(&g_cur[dst], 1);
    g_col[pos] = src;
}

// ---------------- fused softmax (no max pass) + aggregate + bias + LN + ReLU --
__global__ __launch_bounds__(256) void aggregate_kernel(float* __restrict__ out,
                                                        const float* __restrict__ bias,
                                                        const float* __restrict__ gamma,
                                                        const float* __restrict__ beta,
                                                        int n) {
    int d = (blockIdx.x * blockDim.x + threadIdx.x) >> 5;
    int lane = threadIdx.x & 31;
    if (d >= n) return;

    const int off = g_off[d];
    const int deg = g_off[d + 1] - off;

    float4 t0 = *(const float4*)(g_adst + d * HEADS);
    float4 t1 = *(const float4*)(g_adst + d * HEADS + 4);
    float adst8[8] = {t0.x, t0.y, t0.z, t0.w, t1.x, t1.y, t1.z, t1.w};
    float4 u0 = *(const float4*)(g_asrc + d * HEADS);
    float4 u1 = *(const float4*)(g_asrc + d * HEADS + 4);
    float asd[8] = {u0.x, u0.y, u0.z, u0.w, u1.x, u1.y, u1.z, u1.w};

    // ---- denom pass (logits are O(10); exp without max subtraction is safe) ----
    float sm[8] = {0.f, 0.f, 0.f, 0.f, 0.f, 0.f, 0.f, 0.f};
    for (int i = lane; i < deg; i += 32) {
        int s = __ldg(g_col + off + i);
        float4 a0 = *(const float4*)(g_asrc + s * HEADS);
        float4 a1 = *(const float4*)(g_asrc + s * HEADS + 4);
        sm[0] += __expf(leaky(a0.x + adst8[0]));
        sm[1] += __expf(leaky(a0.y + adst8[1]));
        sm[2] += __expf(leaky(a0.z + adst8[2]));
        sm[3] += __expf(leaky(a0.w + adst8[3]));
        sm[4] += __expf(leaky(a1.x + adst8[4]));
        sm[5] += __expf(leaky(a1.y + adst8[5]));
        sm[6] += __expf(leaky(a1.z + adst8[6]));
        sm[7] += __expf(leaky(a1.w + adst8[7]));
    }
#pragma unroll
    for (int o = 16; o; o >>= 1)
#pragma unroll
        for (int k = 0; k < 8; ++k)
            sm[k] += __shfl_xor_sync(0xffffffffu, sm[k], o);
#pragma unroll
    for (int k = 0; k < 8; ++k)
        sm[k] += __expf(leaky(asd[k] + adst8[k]));   // self-loop term

    const int lk = lane & 7;
    const int myhead = lane >> 2;
    float inv_lk = 0.f, adst_lk = 0.f;
    float inv_h = 0.f, adst_h = 0.f, asd_h = 0.f;
#pragma unroll
    for (int k = 0; k < 8; ++k) {
        float invk = 1.f / sm[k];
        if (lk == k)     { inv_lk = invk; adst_lk = adst8[k]; }
        if (myhead == k) { inv_h = invk; adst_h = adst8[k]; asd_h = asd[k]; }
    }

    // ---- gather-accumulate (self-loop first), 2-way unrolled ----
    float sa = __expf(leaky(asd_h + adst_h)) * inv_h;
    const float4* hd = (const float4*)(g_h + (size_t)d * FOUT) + lane * 2;
    float4 v0 = __ldg(hd), v1 = __ldg(hd + 1);
    float4 acc0 = make_float4(v0.x * sa, v0.y * sa, v0.z * sa, v0.w * sa);
    float4 acc1 = make_float4(v1.x * sa, v1.y * sa, v1.z * sa, v1.w * sa);

    int j = 0;
    for (; j + 2 <= deg; j += 2) {
        int s0 = __ldg(g_col + off + j);
        int s1 = __ldg(g_col + off + j + 1);
        float a0 = __ldg(g_asrc + s0 * HEADS + lk);
        float a1 = __ldg(g_asrc + s1 * HEADS + lk);
        const float4* h0 = (const float4*)(g_h + (size_t)s0 * FOUT) + lane * 2;
        const float4* h1 = (const float4*)(g_h + (size_t)s1 * FOUT) + lane * 2;
        float4 w00 = __ldg(h0), w01 = __ldg(h0 + 1);
        float4 w10 = __ldg(h1), w11 = __ldg(h1 + 1);
        float al0 = __expf(leaky(a0 + adst_lk)) * inv_lk;
        float al1 = __expf(leaky(a1 + adst_lk)) * inv_lk;
        float av0 = __shfl_sync(0xffffffffu, al0, myhead);
        float av1 = __shfl_sync(0xffffffffu, al1, myhead);
        acc0.x += w00.x * av0; acc0.y += w00.y * av0;
        acc0.z += w00.z * av0; acc0.w += w00.w * av0;
        acc1.x += w01.x * av0; acc1.y += w01.y * av0;
        acc1.z += w01.z * av0; acc1.w += w01.w * av0;
        acc0.x += w10.x * av1; acc0.y += w10.y * av1;
        acc0.z += w10.z * av1; acc0.w += w10.w * av1;
        acc1.x += w11.x * av1; acc1.y += w11.y * av1;
        acc1.z += w11.z * av1; acc1.w += w11.w * av1;
    }
    if (j < deg) {
        int s0 = __ldg(g_col + off + j);
        float a0 = __ldg(g_asrc + s0 * HEADS + lk);
        const float4* h0 = (const float4*)(g_h + (size_t)s0 * FOUT) + lane * 2;
        float4 w00 = __ldg(h0), w01 = __ldg(h0 + 1);
        float al0 = __expf(leaky(a0 + adst_lk)) * inv_lk;
        float av0 = __shfl_sync(0xffffffffu, al0, myhead);
        acc0.x += w00.x * av0; acc0.y += w00.y * av0;
        acc0.z += w00.z * av0; acc0.w += w00.w * av0;
        acc1.x += w01.x * av0; acc1.y += w01.y * av0;
        acc1.z += w01.z * av0; acc1.w += w01.w * av0;
    }

    // ---- bias + LayerNorm + ReLU ----
    const int c0 = lane * 8;
    float4 b0 = *(const float4*)(bias + c0);
    float4 b1 = *(const float4*)(bias + c0 + 4);
    acc0.x += b0.x; acc0.y += b0.y; acc0.z += b0.z; acc0.w += b0.w;
    acc1.x += b1.x; acc1.y += b1.y; acc1.z += b1.z; acc1.w += b1.w;

    float s = acc0.x + acc0.y + acc0.z + acc0.w + acc1.x + acc1.y + acc1.z + acc1.w;
    float q = acc0.x * acc0.x + acc0.y * acc0.y + acc0.z * acc0.z + acc0.w * acc0.w +
              acc1.x * acc1.x + acc1.y * acc1.y + acc1.z * acc1.z + acc1.w * acc1.w;
#pragma unroll
    for (int o = 16; o; o >>= 1) {
        s += __shfl_xor_sync(0xffffffffu, s, o);
        q += __shfl_xor_sync(0xffffffffu, q, o);
    }
    float mu = s * (1.f / FOUT);
    float var = q * (1.f / FOUT) - mu * mu;
    float rs = rsqrtf(var + LN_EPS);

    float4 g0 = *(const float4*)(gamma + c0);
    float4 g1 = *(const float4*)(gamma + c0 + 4);
    float4 e0 = *(const float4*)(beta + c0);
    float4 e1 = *(const float4*)(beta + c0 + 4);
    float4 r0, r1;
    r0.x = fmaxf((acc0.x - mu) * rs * g0.x + e0.x, 0.f);
    r0.y = fmaxf((acc0.y - mu) * rs * g0.y + e0.y, 0.f);
    r0.z = fmaxf((acc0.z - mu) * rs * g0.z + e0.z, 0.f);
    r0.w = fmaxf((acc0.w - mu) * rs * g0.w + e0.w, 0.f);
    r1.x = fmaxf((acc1.x - mu) * rs * g1.x + e1.x, 0.f);
    r1.y = fmaxf((acc1.y - mu) * rs * g1.y + e1.y, 0.f);
    r1.z = fmaxf((acc1.z - mu) * rs * g1.z + e1.z, 0.f);
    r1.w = fmaxf((acc1.w - mu) * rs * g1.w + e1.w, 0.f);
    float* row = out + (size_t)d * FOUT + c0;
    *(float4*)row       = r0;
    *(float4*)(row + 4) = r1;
}

// ---------------- launch ------------------------------------------------------
extern "C" void kernel_launch(void* const* d_in, const int* in_sizes, int n_in,
                              void* d_out, int out_size) {
    const float* x       = (const float*)d_in[0];
    const void*  eidx    = d_in[1];
    const float* W       = (const float*)d_in[2];
    const float* att_src = (const float*)d_in[3];
    const float* att_dst = (const float*)d_in[4];
    const float* bias    = (const float*)d_in[5];
    const float* gamma   = (const float*)d_in[6];
    const float* beta    = (const float*)d_in[7];
    float* out = (float*)d_out;

    const int n = in_sizes[0] / FIN;     // 50000
    const int e = in_sizes[1] / 2;       // 800000

    int cnt = 64 < 2 * e ? 64 : 2 * e;
    detect_idx_kernel<<<1, 32>>>((const long long*)eidx, n, cnt);

    xconv_kernel<<<(n * (FIN / 4) + 255) / 256, 256>>>(x, n);
    wconv_kernel<<<(FOUT * FIN + 255) / 256, 256>>>(W);

    dim3 ggrid((n + 127) / 128, FOUT / 128);
    gemm_mma_kernel<<<ggrid, 256>>>(n);

    node_att_kernel<<<(n * 32 + 255) / 256, 256>>>(att_src, att_dst, n);

    const int nb = (n + 255) / 256;      // 196
    zero_cnt_kernel<<<nb, 256>>>(n);
    count_kernel<<<(e + 255) / 256, 256>>>(eidx, e);
    scan1_kernel<<<nb, 256>>>(n);
    scan2_kernel<<<1, 256>>>(nb, n);
    scan3_kernel<<<nb, 256>>>(n);
    fill_kernel<<<(e + 255) / 256, 256>>>(eidx, e);

    aggregate_kernel<<<(n * 32 + 255) / 256, 256>>>(out, bias, gamma, beta, n);
}

// round 9
// speedup vs baseline: 5.8199x; 1.1908x over previous
#include <cuda_runtime.h>
#include <cuda_bf16.h>
#include <cuda_fp16.h>
#include <cstdint>

#define NNODES 50000
#define NEDGES 800000
#define FIN 256
#define FOUT 256
#define HEADS 8
#define CH 32
#define NEG_SLOPE 0.2f
#define LN_EPS 1e-5f

// ---------------- scratch (static device globals) -----------------------------
__device__ __half g_hf[(size_t)NNODES * FOUT];   // h in fp16, 25.6 MB
__device__ __nv_bfloat16 g_wh[FOUT * FIN];       // Wt hi: [n][k]
__device__ __nv_bfloat16 g_wl[FOUT * FIN];       // Wt lo: [n][k]
__device__ float g_asrc[NNODES * HEADS];
__device__ float g_adst[NNODES * HEADS];
__device__ int   g_cnt[NNODES];
__device__ int   g_off[NNODES + 1];
__device__ int   g_cur[NNODES];
__device__ int   g_col[NEDGES];
__device__ int   g_bsum[256];
__device__ int   g_is64;

__device__ __forceinline__ float leaky(float v) {
    return v > 0.f ? v : NEG_SLOPE * v;
}

__device__ __forceinline__ uint32_t smem_u32(const void* p) {
    uint32_t a;
    asm("{ .reg .u64 t; cvta.to.shared.u64 t, %1; cvt.u32.u64 %0, t; }"
        : "=r"(a) : "l"(p));
    return a;
}

// ---------------- int64/int32 edge-index detection ----------------------------
__global__ void detect_idx_kernel(const long long* __restrict__ ei, int n, int cnt) {
    if (threadIdx.x == 0 && blockIdx.x == 0) {
        int ok = 1;
        for (int i = 0; i < cnt; ++i) {
            long long v = ei[i];
            if (v < 0 || v >= (long long)n) { ok = 0; break; }
        }
        g_is64 = ok;
    }
}

__device__ __forceinline__ void load_edge(const void* eidx, int e, int i,
                                          int& src, int& dst) {
    if (g_is64) {
        const long long* p = (const long long*)eidx;
        src = (int)p[i];
        dst = (int)p[(size_t)e + i];
    } else {
        const int* p = (const int*)eidx;
        src = p[i];
        dst = p[e + i];
    }
}

// ---------------- W conversion: fp32 -> bf16 hi/lo, transposed ----------------
__global__ void wconv_kernel(const float* __restrict__ W) {
    int idx = blockIdx.x * blockDim.x + threadIdx.x;
    if (idx >= FOUT * FIN) return;
    int n = idx >> 8;      // out channel
    int k = idx & 255;     // in channel
    float w = W[k * FOUT + n];
    __nv_bfloat16 hi = __float2bfloat16(w);
    __nv_bfloat16 lo = __float2bfloat16(w - __bfloat162float(hi));
    g_wh[n * FIN + k] = hi;
    g_wl[n * FIN + k] = lo;
}

// pack 8 fp32 -> uint4 of 8 bf16 (hi part, or residual-lo part)
__device__ __forceinline__ uint4 cvt8_bf16(float4 v0, float4 v1, bool lo) {
    float f[8] = {v0.x, v0.y, v0.z, v0.w, v1.x, v1.y, v1.z, v1.w};
    unsigned r[4];
#pragma unroll
    for (int i = 0; i < 4; ++i) {
        float fa = f[2 * i], fb = f[2 * i + 1];
        __nv_bfloat16 ha = __float2bfloat16(fa);
        __nv_bfloat16 hb = __float2bfloat16(fb);
        if (lo) {
            ha = __float2bfloat16(fa - __bfloat162float(ha));
            hb = __float2bfloat16(fb - __bfloat162float(hb));
        }
        __nv_bfloat162 t = __nv_bfloat162(ha, hb);
        r[i] = *reinterpret_cast<unsigned*>(&t);
    }
    return make_uint4(r[0], r[1], r[2], r[3]);
}

// ---------------- K1: double-buffered bf16 mma GEMM + fused conv + logits ------
// h = xh@Wh + xl@Wh + xh@Wl ; CTA 128x128, 8 warps x (64x32); h stored fp16;
// per-head attention logits computed in epilogue (each warp column span = 1 head)
#define APITCH 40
#define NITER 24
__global__ __launch_bounds__(256) void gemm_mma_kernel(const float* __restrict__ x,
                                                       const float* __restrict__ att_src,
                                                       const float* __restrict__ att_dst,
                                                       int M) {
    __shared__ __nv_bfloat16 As[2][128][APITCH];
    __shared__ __nv_bfloat16 Bs[2][128][APITCH];

    const int tid = threadIdx.x;
    const int warp = tid >> 5;
    const int lane = tid & 31;
    const int wm = warp & 1;
    const int wn = warp >> 1;
    const int m0 = blockIdx.x * 128;
    const int n0 = blockIdx.y * 128;

    float acc[4][4][4];
#pragma unroll
    for (int a = 0; a < 4; ++a)
#pragma unroll
        for (int b = 0; b < 4; ++b)
#pragma unroll
            for (int c = 0; c < 4; ++c) acc[a][b][c] = 0.f;

    const int lrow = tid >> 1;            // 0..127
    const int lk = (tid & 1) * 16;        // 0 or 16

    const int arow = wm * 64 + (lane & 7) + ((lane >> 3) & 1) * 8;
    const int acol = (lane >> 4) * 8;
    const int l16 = lane & 15;
    const int brow = wn * 32 + (l16 & 7);
    const int bcol = ((l16 >> 3) & 1) * 8;

    const int gr = m0 + lrow;
    const bool rok = gr < M;

    // ---- tile loader: iteration it in [0,24): pass p=it/8, kchunk=(it%8)*32 ----
    auto load_tiles = [&](int it, uint4& a0, uint4& a1, uint4& b0, uint4& b1) {
        const int p = it >> 3;
        const int kc = (it & 7) << 5;
        const bool lo = (p == 1);
        const __nv_bfloat16* Bg = (p == 2) ? g_wl : g_wh;
        if (rok) {
            const float* ap = x + (size_t)gr * FIN + kc + lk;
            float4 v0 = __ldg((const float4*)ap);
            float4 v1 = __ldg((const float4*)(ap + 4));
            float4 v2 = __ldg((const float4*)(ap + 8));
            float4 v3 = __ldg((const float4*)(ap + 12));
            a0 = cvt8_bf16(v0, v1, lo);
            a1 = cvt8_bf16(v2, v3, lo);
        } else {
            a0 = make_uint4(0, 0, 0, 0);
            a1 = make_uint4(0, 0, 0, 0);
        }
        const __nv_bfloat16* bp = Bg + (size_t)(n0 + lrow) * FIN + kc + lk;
        b0 = *(const uint4*)bp;
        b1 = *(const uint4*)(bp + 8);
    };

    // prologue: fill buffer 0
    {
        uint4 a0, a1, b0, b1;
        load_tiles(0, a0, a1, b0, b1);
        *(uint4*)&As[0][lrow][lk]     = a0;
        *(uint4*)&As[0][lrow][lk + 8] = a1;
        *(uint4*)&Bs[0][lrow][lk]     = b0;
        *(uint4*)&Bs[0][lrow][lk + 8] = b1;
    }
    __syncthreads();

    for (int it = 0; it < NITER; ++it) {
        const int cur = it & 1;
        const int nxt = cur ^ 1;
        const bool more = (it + 1 < NITER);
        uint4 pa0, pa1, pb0, pb1;
        if (more) load_tiles(it + 1, pa0, pa1, pb0, pb1);

#pragma unroll
        for (int ks = 0; ks < 32; ks += 16) {
            uint32_t a[4][4];
#pragma unroll
            for (int mf = 0; mf < 4; ++mf) {
                uint32_t ad = smem_u32(&As[cur][arow + mf * 16][ks + acol]);
                asm volatile(
                    "ldmatrix.sync.aligned.m8n8.x4.shared.b16 {%0,%1,%2,%3}, [%4];"
                    : "=r"(a[mf][0]), "=r"(a[mf][1]), "=r"(a[mf][2]), "=r"(a[mf][3])
                    : "r"(ad));
            }
            uint32_t b[4][2];
#pragma unroll
            for (int nf = 0; nf < 4; ++nf) {
                uint32_t bd = smem_u32(&Bs[cur][brow + nf * 8][ks + bcol]);
                asm volatile(
                    "ldmatrix.sync.aligned.m8n8.x2.shared.b16 {%0,%1}, [%2];"
                    : "=r"(b[nf][0]), "=r"(b[nf][1]) : "r"(bd));
            }
#pragma unroll
            for (int mf = 0; mf < 4; ++mf)
#pragma unroll
                for (int nf = 0; nf < 4; ++nf) {
                    asm volatile(
                        "mma.sync.aligned.m16n8k16.row.col.f32.bf16.bf16.f32 "
                        "{%0,%1,%2,%3}, {%4,%5,%6,%7}, {%8,%9}, {%0,%1,%2,%3};"
                        : "+f"(acc[mf][nf][0]), "+f"(acc[mf][nf][1]),
                          "+f"(acc[mf][nf][2]), "+f"(acc[mf][nf][3])
                        : "r"(a[mf][0]), "r"(a[mf][1]), "r"(a[mf][2]), "r"(a[mf][3]),
                          "r"(b[nf][0]), "r"(b[nf][1]));
                }
        }

        if (more) {
            *(uint4*)&As[nxt][lrow][lk]     = pa0;
            *(uint4*)&As[nxt][lrow][lk + 8] = pa1;
            *(uint4*)&Bs[nxt][lrow][lk]     = pb0;
            *(uint4*)&Bs[nxt][lrow][lk + 8] = pb1;
        }
        __syncthreads();
    }

    // ---- epilogue: store h (fp16) + fused per-head attention logits ----
    const int rbase = m0 + wm * 64 + (lane >> 2);
    const int cbase = n0 + wn * 32 + (lane & 3) * 2;
    const int head = (n0 >> 5) + wn;   // warp's 32-col span = exactly one head

    float asv[8], adv[8];
#pragma unroll
    for (int nf = 0; nf < 4; ++nf)
#pragma unroll
        for (int t = 0; t < 2; ++t) {
            int c = (lane & 3) * 2 + nf * 8 + t;
            asv[nf * 2 + t] = __ldg(att_src + head * CH + c);
            adv[nf * 2 + t] = __ldg(att_dst + head * CH + c);
        }

#pragma unroll
    for (int mf = 0; mf < 4; ++mf) {
#pragma unroll
        for (int sub = 0; sub < 2; ++sub) {
            int r = rbase + mf * 16 + sub * 8;
            float ds = 0.f, dd = 0.f;
#pragma unroll
            for (int nf = 0; nf < 4; ++nf) {
                float v0 = acc[mf][nf][sub * 2 + 0];
                float v1 = acc[mf][nf][sub * 2 + 1];
                if (r < M) {
                    __half2 hv = __floats2half2_rn(v0, v1);
                    *(__half2*)(g_hf + (size_t)r * FOUT + cbase + nf * 8) = hv;
                }
                ds += v0 * asv[nf * 2] + v1 * asv[nf * 2 + 1];
                dd += v0 * adv[nf * 2] + v1 * adv[nf * 2 + 1];
            }
            ds += __shfl_xor_sync(0xffffffffu, ds, 1);
            ds += __shfl_xor_sync(0xffffffffu, ds, 2);
            dd += __shfl_xor_sync(0xffffffffu, dd, 1);
            dd += __shfl_xor_sync(0xffffffffu, dd, 2);
            if ((lane & 3) == 0 && r < M) {
                g_asrc[r * HEADS + head] = ds;
                g_adst[r * HEADS + head] = dd;
            }
        }
    }
}

// ---------------- CSR build ----------------------------------------------------
__global__ void zero_cnt_kernel(int n) {
    int i = blockIdx.x * blockDim.x + threadIdx.x;
    if (i < n) g_cnt[i] = 0;
}

__global__ void count_kernel(const void* __restrict__ eidx, int e) {
    int i = blockIdx.x * blockDim.x + threadIdx.x;
    if (i >= e) return;
    int src, dst;
    load_edge(eidx, e, i, src, dst);
    atomicAdd(&g_cnt[dst], 1);
}

__global__ __launch_bounds__(256) void scan1_kernel(int n) {
    __shared__ int sh[256];
    int i = blockIdx.x * 256 + threadIdx.x;
    sh[threadIdx.x] = (i < n) ? g_cnt[i] : 0;
    __syncthreads();
    for (int o = 128; o; o >>= 1) {
        if (threadIdx.x < o) sh[threadIdx.x] += sh[threadIdx.x + o];
        __syncthreads();
    }
    if (threadIdx.x == 0) g_bsum[blockIdx.x] = sh[0];
}

__global__ __launch_bounds__(256) void scan2_kernel(int nb, int n) {
    __shared__ int sh[256];
    int t = threadIdx.x;
    sh[t] = (t < nb) ? g_bsum[t] : 0;
    __syncthreads();
    for (int o = 1; o < 256; o <<= 1) {
        int v = (t >= o) ? sh[t - o] : 0;
        __syncthreads();
        sh[t] += v;
        __syncthreads();
    }
    if (t < nb) g_bsum[t] = sh[t];       // inclusive
    if (t == 255) g_off[n] = sh[nb - 1];
}

__global__ __launch_bounds__(256) void scan3_kernel(int n) {
    __shared__ int sh[256];
    int t = threadIdx.x;
    int i = blockIdx.x * 256 + t;
    int v = (i < n) ? g_cnt[i] : 0;
    sh[t] = v;
    __syncthreads();
    for (int o = 1; o < 256; o <<= 1) {
        int u = (t >= o) ? sh[t - o] : 0;
        __syncthreads();
        sh[t] += u;
        __syncthreads();
    }
    int bex = (blockIdx.x > 0) ? g_bsum[blockIdx.x - 1] : 0;
    if (i < n) {
        int off = bex + sh[t] - v;   // exclusive
        g_off[i] = off;
        g_cur[i] = off;
    }
}

__global__ void fill_kernel(const void* __restrict__ eidx, int e) {
    int i = blockIdx.x * blockDim.x + threadIdx.x;
    if (i >= e) return;
    int src, dst;
    load_edge(eidx, e, i, src, dst);
    int pos = atomicAdd(&g_cur[dst], 1);
    g_col[pos] = src;
}

// unpack 8 fp16 -> two float4
__device__ __forceinline__ void h8_to_f(uint4 hv, float4& f0, float4& f1) {
    const __half2* hp = (const __half2*)&hv;
    float2 a = __half22float2(hp[0]);
    float2 b = __half22float2(hp[1]);
    float2 c = __half22float2(hp[2]);
    float2 d = __half22float2(hp[3]);
    f0 = make_float4(a.x, a.y, b.x, b.y);
    f1 = make_float4(c.x, c.y, d.x, d.y);
}

// ---------------- fused softmax (no max pass) + aggregate + bias + LN + ReLU --
__global__ __launch_bounds__(256) void aggregate_kernel(float* __restrict__ out,
                                                        const float* __restrict__ bias,
                                                        const float* __restrict__ gamma,
                                                        const float* __restrict__ beta,
                                                        int n) {
    int d = (blockIdx.x * blockDim.x + threadIdx.x) >> 5;
    int lane = threadIdx.x & 31;
    if (d >= n) return;

    const int off = g_off[d];
    const int deg = g_off[d + 1] - off;

    float4 t0 = *(const float4*)(g_adst + d * HEADS);
    float4 t1 = *(const float4*)(g_adst + d * HEADS + 4);
    float adst8[8] = {t0.x, t0.y, t0.z, t0.w, t1.x, t1.y, t1.z, t1.w};
    float4 u0 = *(const float4*)(g_asrc + d * HEADS);
    float4 u1 = *(const float4*)(g_asrc + d * HEADS + 4);
    float asd[8] = {u0.x, u0.y, u0.z, u0.w, u1.x, u1.y, u1.z, u1.w};

    // ---- denom pass (logits are O(10); exp without max subtraction is safe) ----
    float sm[8] = {0.f, 0.f, 0.f, 0.f, 0.f, 0.f, 0.f, 0.f};
    for (int i = lane; i < deg; i += 32) {
        int s = __ldg(g_col + off + i);
        float4 a0 = *(const float4*)(g_asrc + s * HEADS);
        float4 a1 = *(const float4*)(g_asrc + s * HEADS + 4);
        sm[0] += __expf(leaky(a0.x + adst8[0]));
        sm[1] += __expf(leaky(a0.y + adst8[1]));
        sm[2] += __expf(leaky(a0.z + adst8[2]));
        sm[3] += __expf(leaky(a0.w + adst8[3]));
        sm[4] += __expf(leaky(a1.x + adst8[4]));
        sm[5] += __expf(leaky(a1.y + adst8[5]));
        sm[6] += __expf(leaky(a1.z + adst8[6]));
        sm[7] += __expf(leaky(a1.w + adst8[7]));
    }
#pragma unroll
    for (int o = 16; o; o >>= 1)
#pragma unroll
        for (int k = 0; k < 8; ++k)
            sm[k] += __shfl_xor_sync(0xffffffffu, sm[k], o);
#pragma unroll
    for (int k = 0; k < 8; ++k)
        sm[k] += __expf(leaky(asd[k] + adst8[k]));   // self-loop term

    const int lk = lane & 7;
    const int myhead = lane >> 2;
    float inv_lk = 0.f, adst_lk = 0.f;
    float inv_h = 0.f, adst_h = 0.f, asd_h = 0.f;
#pragma unroll
    for (int k = 0; k < 8; ++k) {
        float invk = 1.f / sm[k];
        if (lk == k)     { inv_lk = invk; adst_lk = adst8[k]; }
        if (myhead == k) { inv_h = invk; adst_h = adst8[k]; asd_h = asd[k]; }
    }

    // ---- gather-accumulate over fp16 h (self-loop first), 2-way unrolled ----
    float sa = __expf(leaky(asd_h + adst_h)) * inv_h;
    uint4 shv = __ldg((const uint4*)(g_hf + (size_t)d * FOUT + lane * 8));
    float4 v0, v1;
    h8_to_f(shv, v0, v1);
    float4 acc0 = make_float4(v0.x * sa, v0.y * sa, v0.z * sa, v0.w * sa);
    float4 acc1 = make_float4(v1.x * sa, v1.y * sa, v1.z * sa, v1.w * sa);

    int j = 0;
    for (; j + 2 <= deg; j += 2) {
        int s0 = __ldg(g_col + off + j);
        int s1 = __ldg(g_col + off + j + 1);
        float a0 = __ldg(g_asrc + s0 * HEADS + lk);
        float a1 = __ldg(g_asrc + s1 * HEADS + lk);
        uint4 hv0 = __ldg((const uint4*)(g_hf + (size_t)s0 * FOUT + lane * 8));
        uint4 hv1 = __ldg((const uint4*)(g_hf + (size_t)s1 * FOUT + lane * 8));
        float al0 = __expf(leaky(a0 + adst_lk)) * inv_lk;
        float al1 = __expf(leaky(a1 + adst_lk)) * inv_lk;
        float av0 = __shfl_sync(0xffffffffu, al0, myhead);
        float av1 = __shfl_sync(0xffffffffu, al1, myhead);
        float4 w00, w01, w10, w11;
        h8_to_f(hv0, w00, w01);
        h8_to_f(hv1, w10, w11);
        acc0.x += w00.x * av0; acc0.y += w00.y * av0;
        acc0.z += w00.z * av0; acc0.w += w00.w * av0;
        acc1.x += w01.x * av0; acc1.y += w01.y * av0;
        acc1.z += w01.z * av0; acc1.w += w01.w * av0;
        acc0.x += w10.x * av1; acc0.y += w10.y * av1;
        acc0.z += w10.z * av1; acc0.w += w10.w * av1;
        acc1.x += w11.x * av1; acc1.y += w11.y * av1;
        acc1.z += w11.z * av1; acc1.w += w11.w * av1;
    }
    if (j < deg) {
        int s0 = __ldg(g_col + off + j);
        float a0 = __ldg(g_asrc + s0 * HEADS + lk);
        uint4 hv0 = __ldg((const uint4*)(g_hf + (size_t)s0 * FOUT + lane * 8));
        float al0 = __expf(leaky(a0 + adst_lk)) * inv_lk;
        float av0 = __shfl_sync(0xffffffffu, al0, myhead);
        float4 w00, w01;
        h8_to_f(hv0, w00, w01);
        acc0.x += w00.x * av0; acc0.y += w00.y * av0;
        acc0.z += w00.z * av0; acc0.w += w00.w * av0;
        acc1.x += w01.x * av0; acc1.y += w01.y * av0;
        acc1.z += w01.z * av0; acc1.w += w01.w * av0;
    }

    // ---- bias + LayerNorm + ReLU ----
    const int c0 = lane * 8;
    float4 b0 = *(const float4*)(bias + c0);
    float4 b1 = *(const float4*)(bias + c0 + 4);
    acc0.x += b0.x; acc0.y += b0.y; acc0.z += b0.z; acc0.w += b0.w;
    acc1.x += b1.x; acc1.y += b1.y; acc1.z += b1.z; acc1.w += b1.w;

    float s = acc0.x + acc0.y + acc0.z + acc0.w + acc1.x + acc1.y + acc1.z + acc1.w;
    float q = acc0.x * acc0.x + acc0.y * acc0.y + acc0.z * acc0.z + acc0.w * acc0.w +
              acc1.x * acc1.x + acc1.y * acc1.y + acc1.z * acc1.z + acc1.w * acc1.w;
#pragma unroll
    for (int o = 16; o; o >>= 1) {
        s += __shfl_xor_sync(0xffffffffu, s, o);
        q += __shfl_xor_sync(0xffffffffu, q, o);
    }
    float mu = s * (1.f / FOUT);
    float var = q * (1.f / FOUT) - mu * mu;
    float rs = rsqrtf(var + LN_EPS);

    float4 g0 = *(const float4*)(gamma + c0);
    float4 g1 = *(const float4*)(gamma + c0 + 4);
    float4 e0 = *(const float4*)(beta + c0);
    float4 e1 = *(const float4*)(beta + c0 + 4);
    float4 r0, r1;
    r0.x = fmaxf((acc0.x - mu) * rs * g0.x + e0.x, 0.f);
    r0.y = fmaxf((acc0.y - mu) * rs * g0.y + e0.y, 0.f);
    r0.z = fmaxf((acc0.z - mu) * rs * g0.z + e0.z, 0.f);
    r0.w = fmaxf((acc0.w - mu) * rs * g0.w + e0.w, 0.f);
    r1.x = fmaxf((acc1.x - mu) * rs * g1.x + e1.x, 0.f);
    r1.y = fmaxf((acc1.y - mu) * rs * g1.y + e1.y, 0.f);
    r1.z = fmaxf((acc1.z - mu) * rs * g1.z + e1.z, 0.f);
    r1.w = fmaxf((acc1.w - mu) * rs * g1.w + e1.w, 0.f);
    float* row = out + (size_t)d * FOUT + c0;
    *(float4*)row       = r0;
    *(float4*)(row + 4) = r1;
}

// ---------------- launch ------------------------------------------------------
extern "C" void kernel_launch(void* const* d_in, const int* in_sizes, int n_in,
                              void* d_out, int out_size) {
    const float* x       = (const float*)d_in[0];
    const void*  eidx    = d_in[1];
    const float* W       = (const float*)d_in[2];
    const float* att_src = (const float*)d_in[3];
    const float* att_dst = (const float*)d_in[4];
    const float* bias    = (const float*)d_in[5];
    const float* gamma   = (const float*)d_in[6];
    const float* beta    = (const float*)d_in[7];
    float* out = (float*)d_out;

    const int n = in_sizes[0] / FIN;     // 50000
    const int e = in_sizes[1] / 2;       // 800000

    int cnt = 64 < 2 * e ? 64 : 2 * e;
    detect_idx_kernel<<<1, 32>>>((const long long*)eidx, n, cnt);

    wconv_kernel<<<(FOUT * FIN + 255) / 256, 256>>>(W);

    dim3 ggrid((n + 127) / 128, FOUT / 128);
    gemm_mma_kernel<<<ggrid, 256>>>(x, att_src, att_dst, n);

    const int nb = (n + 255) / 256;      // 196
    zero_cnt_kernel<<<nb, 256>>>(n);
    count_kernel<<<(e + 255) / 256, 256>>>(eidx, e);
    scan1_kernel<<<nb, 256>>>(n);
    scan2_kernel<<<1, 256>>>(nb, n);
    scan3_kernel<<<nb, 256>>>(n);
    fill_kernel<<<(e + 255) / 256, 256>>>(eidx, e);

    aggregate_kernel<<<(n * 32 + 255) / 256, 256>>>(out, bias, gamma, beta, n);
}

// round 13
// speedup vs baseline: 6.3079x; 1.0839x over previous
#include <cuda_runtime.h>
#include <cuda_bf16.h>
#include <cuda_fp16.h>
#include <cstdint>

#define NNODES 50000
#define NEDGES 800000
#define FIN 256
#define FOUT 256
#define HEADS 8
#define CH 32
#define NEG_SLOPE 0.2f
#define LN_EPS 1e-5f

// ---------------- scratch (static device globals) -----------------------------
__device__ __half g_hf[(size_t)NNODES * FOUT];   // h in fp16, 25.6 MB
__device__ __nv_bfloat16 g_wh[FOUT * FIN];       // Wt hi: [n][k]
__device__ __nv_bfloat16 g_wl[FOUT * FIN];       // Wt lo: [n][k]
__device__ float g_asrc[NNODES * HEADS];
__device__ float g_adst[NNODES * HEADS];
__device__ int   g_cnt[NNODES];
__device__ int   g_off[NNODES + 1];
__device__ int   g_cur[NNODES];
__device__ int   g_col[NEDGES];
__device__ int   g_bsum[256];
__device__ int   g_is64;

__device__ __forceinline__ float leaky(float v) {
    return v > 0.f ? v : NEG_SLOPE * v;
}

__device__ __forceinline__ uint32_t smem_u32(const void* p) {
    uint32_t a;
    asm("{ .reg .u64 t; cvta.to.shared.u64 t, %1; cvt.u32.u64 %0, t; }"
        : "=r"(a) : "l"(p));
    return a;
}

// ---------------- int64/int32 edge-index detection ----------------------------
__global__ void detect_idx_kernel(const long long* __restrict__ ei, int n, int cnt) {
    if (threadIdx.x == 0 && blockIdx.x == 0) {
        int ok = 1;
        for (int i = 0; i < cnt; ++i) {
            long long v = ei[i];
            if (v < 0 || v >= (long long)n) { ok = 0; break; }
        }
        g_is64 = ok;
    }
}

__device__ __forceinline__ void load_edge(const void* eidx, int e, int i,
                                          int& src, int& dst) {
    if (g_is64) {
        const long long* p = (const long long*)eidx;
        src = (int)p[i];
        dst = (int)p[(size_t)e + i];
    } else {
        const int* p = (const int*)eidx;
        src = p[i];
        dst = p[e + i];
    }
}

// ---------------- fused: W fp32 -> bf16 hi/lo transposed + zero cnt -----------
__global__ void wz_kernel(const float* __restrict__ W, int n) {
    int idx = blockIdx.x * blockDim.x + threadIdx.x;
    if (idx < FOUT * FIN) {
        int nn = idx >> 8;     // out channel
        int k = idx & 255;     // in channel
        float w = W[k * FOUT + nn];
        __nv_bfloat16 hi = __float2bfloat16(w);
        __nv_bfloat16 lo = __float2bfloat16(w - __bfloat162float(hi));
        g_wh[nn * FIN + k] = hi;
        g_wl[nn * FIN + k] = lo;
    }
    if (idx < n) g_cnt[idx] = 0;
}

// pack 8 fp32 -> uint4 of 8 bf16 (hi part, or residual-lo part)
__device__ __forceinline__ uint4 cvt8_bf16(float4 v0, float4 v1, bool lo) {
    float f[8] = {v0.x, v0.y, v0.z, v0.w, v1.x, v1.y, v1.z, v1.w};
    unsigned r[4];
#pragma unroll
    for (int i = 0; i < 4; ++i) {
        float fa = f[2 * i], fb = f[2 * i + 1];
        __nv_bfloat16 ha = __float2bfloat16(fa);
        __nv_bfloat16 hb = __float2bfloat16(fb);
        if (lo) {
            ha = __float2bfloat16(fa - __bfloat162float(ha));
            hb = __float2bfloat16(fb - __bfloat162float(hb));
        }
        __nv_bfloat162 t = __nv_bfloat162(ha, hb);
        r[i] = *reinterpret_cast<unsigned*>(&t);
    }
    return make_uint4(r[0], r[1], r[2], r[3]);
}

// ---------------- K1: double-buffered bf16 mma GEMM + fused conv + logits ------
// h = xh@Wh + xl@Wh + xh@Wl ; CTA 128x128; h stored fp16;
// per-head att logits fused in epilogue
#define APITCH 40
#define NITER 24
__global__ __launch_bounds__(256) void gemm_mma_kernel(const float* __restrict__ x,
                                                       const float* __restrict__ att_src,
                                                       const float* __restrict__ att_dst,
                                                       int M) {
    __shared__ __nv_bfloat16 As[2][128][APITCH];
    __shared__ __nv_bfloat16 Bs[2][128][APITCH];

    const int tid = threadIdx.x;
    const int warp = tid >> 5;
    const int lane = tid & 31;
    const int wm = warp & 1;
    const int wn = warp >> 1;
    const int m0 = blockIdx.x * 128;
    const int n0 = blockIdx.y * 128;

    float acc[4][4][4];
#pragma unroll
    for (int a = 0; a < 4; ++a)
#pragma unroll
        for (int b = 0; b < 4; ++b)
#pragma unroll
            for (int c = 0; c < 4; ++c) acc[a][b][c] = 0.f;

    const int lrow = tid >> 1;            // 0..127
    const int lk = (tid & 1) * 16;        // 0 or 16

    const int arow = wm * 64 + (lane & 7) + ((lane >> 3) & 1) * 8;
    const int acol = (lane >> 4) * 8;
    const int l16 = lane & 15;
    const int brow = wn * 32 + (l16 & 7);
    const int bcol = ((l16 >> 3) & 1) * 8;

    const int gr = m0 + lrow;
    const bool rok = gr < M;

    // it in [0,24): term t=it/8 (0: xh*Wh, 1: xl*Wh, 2: xh*Wl), kchunk=(it%8)*32
    auto load_tiles = [&](int it, uint4& a0, uint4& a1, uint4& b0, uint4& b1) {
        const int t = it >> 3;
        const int kc = (it & 7) << 5;
        const bool alo = (t == 1);
        const __nv_bfloat16* Bg = (t == 2) ? g_wl : g_wh;
        if (rok) {
            const float* ap = x + (size_t)gr * FIN + kc + lk;
            float4 v0 = __ldg((const float4*)ap);
            float4 v1 = __ldg((const float4*)(ap + 4));
            float4 v2 = __ldg((const float4*)(ap + 8));
            float4 v3 = __ldg((const float4*)(ap + 12));
            a0 = cvt8_bf16(v0, v1, alo);
            a1 = cvt8_bf16(v2, v3, alo);
        } else {
            a0 = make_uint4(0, 0, 0, 0);
            a1 = make_uint4(0, 0, 0, 0);
        }
        const __nv_bfloat16* bp = Bg + (size_t)(n0 + lrow) * FIN + kc + lk;
        b0 = *(const uint4*)bp;
        b1 = *(const uint4*)(bp + 8);
    };

    {
        uint4 a0, a1, b0, b1;
        load_tiles(0, a0, a1, b0, b1);
        *(uint4*)&As[0][lrow][lk]     = a0;
        *(uint4*)&As[0][lrow][lk + 8] = a1;
        *(uint4*)&Bs[0][lrow][lk]     = b0;
        *(uint4*)&Bs[0][lrow][lk + 8] = b1;
    }
    __syncthreads();

    for (int it = 0; it < NITER; ++it) {
        const int cur = it & 1;
        const int nxt = cur ^ 1;
        const bool more = (it + 1 < NITER);
        uint4 pa0, pa1, pb0, pb1;
        if (more) load_tiles(it + 1, pa0, pa1, pb0, pb1);

#pragma unroll
        for (int ks = 0; ks < 32; ks += 16) {
            uint32_t a[4][4];
#pragma unroll
            for (int mf = 0; mf < 4; ++mf) {
                uint32_t ad = smem_u32(&As[cur][arow + mf * 16][ks + acol]);
                asm volatile(
                    "ldmatrix.sync.aligned.m8n8.x4.shared.b16 {%0,%1,%2,%3}, [%4];"
                    : "=r"(a[mf][0]), "=r"(a[mf][1]), "=r"(a[mf][2]), "=r"(a[mf][3])
                    : "r"(ad));
            }
            uint32_t b[4][2];
#pragma unroll
            for (int nf = 0; nf < 4; ++nf) {
                uint32_t bd = smem_u32(&Bs[cur][brow + nf * 8][ks + bcol]);
                asm volatile(
                    "ldmatrix.sync.aligned.m8n8.x2.shared.b16 {%0,%1}, [%2];"
                    : "=r"(b[nf][0]), "=r"(b[nf][1]) : "r"(bd));
            }
#pragma unroll
            for (int mf = 0; mf < 4; ++mf)
#pragma unroll
                for (int nf = 0; nf < 4; ++nf) {
                    asm volatile(
                        "mma.sync.aligned.m16n8k16.row.col.f32.bf16.bf16.f32 "
                        "{%0,%1,%2,%3}, {%4,%5,%6,%7}, {%8,%9}, {%0,%1,%2,%3};"
                        : "+f"(acc[mf][nf][0]), "+f"(acc[mf][nf][1]),
                          "+f"(acc[mf][nf][2]), "+f"(acc[mf][nf][3])
                        : "r"(a[mf][0]), "r"(a[mf][1]), "r"(a[mf][2]), "r"(a[mf][3]),
                          "r"(b[nf][0]), "r"(b[nf][1]));
                }
        }

        if (more) {
            *(uint4*)&As[nxt][lrow][lk]     = pa0;
            *(uint4*)&As[nxt][lrow][lk + 8] = pa1;
            *(uint4*)&Bs[nxt][lrow][lk]     = pb0;
            *(uint4*)&Bs[nxt][lrow][lk + 8] = pb1;
        }
        __syncthreads();
    }

    // ---- epilogue: store h (fp16) + fused per-head attention logits ----
    const int rbase = m0 + wm * 64 + (lane >> 2);
    const int cbase = n0 + wn * 32 + (lane & 3) * 2;
    const int head = (n0 >> 5) + wn;   // warp's 32-col span = exactly one head

    float asv[8], adv[8];
#pragma unroll
    for (int nf = 0; nf < 4; ++nf)
#pragma unroll
        for (int t = 0; t < 2; ++t) {
            int c = (lane & 3) * 2 + nf * 8 + t;
            asv[nf * 2 + t] = __ldg(att_src + head * CH + c);
            adv[nf * 2 + t] = __ldg(att_dst + head * CH + c);
        }

#pragma unroll
    for (int mf = 0; mf < 4; ++mf) {
#pragma unroll
        for (int sub = 0; sub < 2; ++sub) {
            int r = rbase + mf * 16 + sub * 8;
            float ds = 0.f, dd = 0.f;
#pragma unroll
            for (int nf = 0; nf < 4; ++nf) {
                float v0 = acc[mf][nf][sub * 2 + 0];
                float v1 = acc[mf][nf][sub * 2 + 1];
                if (r < M) {
                    __half2 hv = __floats2half2_rn(v0, v1);
                    *(__half2*)(g_hf + (size_t)r * FOUT + cbase + nf * 8) = hv;
                }
                ds += v0 * asv[nf * 2] + v1 * asv[nf * 2 + 1];
                dd += v0 * adv[nf * 2] + v1 * adv[nf * 2 + 1];
            }
            ds += __shfl_xor_sync(0xffffffffu, ds, 1);
            ds += __shfl_xor_sync(0xffffffffu, ds, 2);
            dd += __shfl_xor_sync(0xffffffffu, dd, 1);
            dd += __shfl_xor_sync(0xffffffffu, dd, 2);
            if ((lane & 3) == 0 && r < M) {
                g_asrc[r * HEADS + head] = ds;
                g_adst[r * HEADS + head] = dd;
            }
        }
    }
}

// ---------------- CSR build ----------------------------------------------------
__global__ void count_kernel(const void* __restrict__ eidx, int e) {
    int i = blockIdx.x * blockDim.x + threadIdx.x;
    if (i >= e) return;
    int dst;
    if (g_is64) dst = (int)((const long long*)eidx)[(size_t)e + i];
    else        dst = ((const int*)eidx)[e + i];
    atomicAdd(&g_cnt[dst], 1);
}

__global__ __launch_bounds__(256) void scan1_kernel(int n) {
    __shared__ int sh[256];
    int i = blockIdx.x * 256 + threadIdx.x;
    sh[threadIdx.x] = (i < n) ? g_cnt[i] : 0;
    __syncthreads();
    for (int o = 128; o; o >>= 1) {
        if (threadIdx.x < o) sh[threadIdx.x] += sh[threadIdx.x + o];
        __syncthreads();
    }
    if (threadIdx.x == 0) g_bsum[blockIdx.x] = sh[0];
}

__global__ __launch_bounds__(256) void scan2_kernel(int nb, int n) {
    __shared__ int sh[256];
    int t = threadIdx.x;
    sh[t] = (t < nb) ? g_bsum[t] : 0;
    __syncthreads();
    for (int o = 1; o < 256; o <<= 1) {
        int v = (t >= o) ? sh[t - o] : 0;
        __syncthreads();
        sh[t] += v;
        __syncthreads();
    }
    if (t < nb) g_bsum[t] = sh[t];       // inclusive
    if (t == 255) g_off[n] = sh[nb - 1];
}

__global__ __launch_bounds__(256) void scan3_kernel(int n) {
    __shared__ int sh[256];
    int t = threadIdx.x;
    int i = blockIdx.x * 256 + t;
    int v = (i < n) ? g_cnt[i] : 0;
    sh[t] = v;
    __syncthreads();
    for (int o = 1; o < 256; o <<= 1) {
        int u = (t >= o) ? sh[t - o] : 0;
        __syncthreads();
        sh[t] += u;
        __syncthreads();
    }
    int bex = (blockIdx.x > 0) ? g_bsum[blockIdx.x - 1] : 0;
    if (i < n) {
        int off = bex + sh[t] - v;   // exclusive
        g_off[i] = off;
        g_cur[i] = off;
    }
}

__global__ void fill_kernel(const void* __restrict__ eidx, int e) {
    int i = blockIdx.x * blockDim.x + threadIdx.x;
    if (i >= e) return;
    int src, dst;
    load_edge(eidx, e, i, src, dst);
    int pos = atomicAdd(&g_cur[dst], 1);
    g_col[pos] = src;
}

// unpack 8 fp16 -> two float4
__device__ __forceinline__ void h8_to_f(uint4 hv, float4& f0, float4& f1) {
    const __half2* hp = (const __half2*)&hv;
    float2 a = __half22float2(hp[0]);
    float2 b = __half22float2(hp[1]);
    float2 c = __half22float2(hp[2]);
    float2 d = __half22float2(hp[3]);
    f0 = make_float4(a.x, a.y, b.x, b.y);
    f1 = make_float4(c.x, c.y, d.x, d.y);
}

// accumulate one edge: fetch weight for my head, fma 8 channels
__device__ __forceinline__ void acc_edge(float wgt, uint4 hv, int myhead,
                                         float4& acc0, float4& acc1) {
    float av = __shfl_sync(0xffffffffu, wgt, myhead);
    float4 f0, f1;
    h8_to_f(hv, f0, f1);
    acc0.x += f0.x * av; acc0.y += f0.y * av;
    acc0.z += f0.z * av; acc0.w += f0.w * av;
    acc1.x += f1.x * av; acc1.y += f1.y * av;
    acc1.z += f1.z * av; acc1.w += f1.w * av;
}

// -------- single-pass aggregate: unnormalized numerator + denominator fused ---
// alpha_e = exp(e)/denom  =>  sum(alpha*h) = sum(exp*h) / sum(exp)
__global__ __launch_bounds__(256) void aggregate_kernel(float* __restrict__ out,
                                                        const float* __restrict__ bias,
                                                        const float* __restrict__ gamma,
                                                        const float* __restrict__ beta,
                                                        int n) {
    int d = (blockIdx.x * blockDim.x + threadIdx.x) >> 5;
    int lane = threadIdx.x & 31;
    if (d >= n) return;

    const int off = g_off[d];
    const int deg = g_off[d + 1] - off;

    float4 t0 = *(const float4*)(g_adst + d * HEADS);
    float4 t1 = *(const float4*)(g_adst + d * HEADS + 4);
    float adst8[8] = {t0.x, t0.y, t0.z, t0.w, t1.x, t1.y, t1.z, t1.w};
    float4 u0 = *(const float4*)(g_asrc + d * HEADS);
    float4 u1 = *(const float4*)(g_asrc + d * HEADS + 4);
    float asd[8] = {u0.x, u0.y, u0.z, u0.w, u1.x, u1.y, u1.z, u1.w};

    const int lk = lane & 7;        // head this lane evaluates weights for
    const int myhead = lane >> 2;   // head owning this lane's 8 output channels
    float adst_lk = 0.f, asd_lk = 0.f;
#pragma unroll
    for (int k = 0; k < 8; ++k)
        if (lk == k) { adst_lk = adst8[k]; asd_lk = asd[k]; }

    // self-loop: weight for head lk; numerator seeded with myhead's self weight
    float sw = __expf(leaky(asd_lk + adst_lk));
    float ws_my = __shfl_sync(0xffffffffu, sw, myhead);

    uint4 shv = __ldg((const uint4*)(g_hf + (size_t)d * FOUT + lane * 8));
    float4 v0, v1;
    h8_to_f(shv, v0, v1);
    float4 acc0 = make_float4(v0.x * ws_my, v0.y * ws_my, v0.z * ws_my, v0.w * ws_my);
    float4 acc1 = make_float4(v1.x * ws_my, v1.y * ws_my, v1.z * ws_my, v1.w * ws_my);

    int j = 0;
    for (; j + 4 <= deg; j += 4) {
        int s0 = __ldg(g_col + off + j);
        int s1 = __ldg(g_col + off + j + 1);
        int s2 = __ldg(g_col + off + j + 2);
        int s3 = __ldg(g_col + off + j + 3);
        float a0 = __ldg(g_asrc + s0 * HEADS + lk);
        float a1 = __ldg(g_asrc + s1 * HEADS + lk);
        float a2 = __ldg(g_asrc + s2 * HEADS + lk);
        float a3 = __ldg(g_asrc + s3 * HEADS + lk);
        uint4 hv0 = __ldg((const uint4*)(g_hf + (size_t)s0 * FOUT + lane * 8));
        uint4 hv1 = __ldg((const uint4*)(g_hf + (size_t)s1 * FOUT + lane * 8));
        uint4 hv2 = __ldg((const uint4*)(g_hf + (size_t)s2 * FOUT + lane * 8));
        uint4 hv3 = __ldg((const uint4*)(g_hf + (size_t)s3 * FOUT + lane * 8));
        float w0 = __expf(leaky(a0 + adst_lk));
        float w1 = __expf(leaky(a1 + adst_lk));
        float w2 = __expf(leaky(a2 + adst_lk));
        float w3 = __expf(leaky(a3 + adst_lk));
        sw += w0 + w1 + w2 + w3;
        acc_edge(w0, hv0, myhead, acc0, acc1);
        acc_edge(w1, hv1, myhead, acc0, acc1);
        acc_edge(w2, hv2, myhead, acc0, acc1);
        acc_edge(w3, hv3, myhead, acc0, acc1);
    }
    for (; j < deg; ++j) {
        int s0 = __ldg(g_col + off + j);
        float a0 = __ldg(g_asrc + s0 * HEADS + lk);
        uint4 hv0 = __ldg((const uint4*)(g_hf + (size_t)s0 * FOUT + lane * 8));
        float w0 = __expf(leaky(a0 + adst_lk));
        sw += w0;
        acc_edge(w0, hv0, myhead, acc0, acc1);
    }

    // normalize by my head's denominator
    float dsum = __shfl_sync(0xffffffffu, sw, myhead);
    float rin = 1.f / dsum;
    acc0.x *= rin; acc0.y *= rin; acc0.z *= rin; acc0.w *= rin;
    acc1.x *= rin; acc1.y *= rin; acc1.z *= rin; acc1.w *= rin;

    // ---- bias + LayerNorm + ReLU ----
    const int c0 = lane * 8;
    float4 b0 = *(const float4*)(bias + c0);
    float4 b1 = *(const float4*)(bias + c0 + 4);
    acc0.x += b0.x; acc0.y += b0.y; acc0.z += b0.z; acc0.w += b0.w;
    acc1.x += b1.x; acc1.y += b1.y; acc1.z += b1.z; acc1.w += b1.w;

    float s = acc0.x + acc0.y + acc0.z + acc0.w + acc1.x + acc1.y + acc1.z + acc1.w;
    float q = acc0.x * acc0.x + acc0.y * acc0.y + acc0.z * acc0.z + acc0.w * acc0.w +
              acc1.x * acc1.x + acc1.y * acc1.y + acc1.z * acc1.z + acc1.w * acc1.w;
#pragma unroll
    for (int o = 16; o; o >>= 1) {
        s += __shfl_xor_sync(0xffffffffu, s, o);
        q += __shfl_xor_sync(0xffffffffu, q, o);
    }
    float mu = s * (1.f / FOUT);
    float var = q * (1.f / FOUT) - mu * mu;
    float rs = rsqrtf(var + LN_EPS);

    float4 g0 = *(const float4*)(gamma + c0);
    float4 g1 = *(const float4*)(gamma + c0 + 4);
    float4 e0 = *(const float4*)(beta + c0);
    float4 e1 = *(const float4*)(beta + c0 + 4);
    float4 r0, r1;
    r0.x = fmaxf((acc0.x - mu) * rs * g0.x + e0.x, 0.f);
    r0.y = fmaxf((acc0.y - mu) * rs * g0.y + e0.y, 0.f);
    r0.z = fmaxf((acc0.z - mu) * rs * g0.z + e0.z, 0.f);
    r0.w = fmaxf((acc0.w - mu) * rs * g0.w + e0.w, 0.f);
    r1.x = fmaxf((acc1.x - mu) * rs * g1.x + e1.x, 0.f);
    r1.y = fmaxf((acc1.y - mu) * rs * g1.y + e1.y, 0.f);
    r1.z = fmaxf((acc1.z - mu) * rs * g1.z + e1.z, 0.f);
    r1.w = fmaxf((acc1.w - mu) * rs * g1.w + e1.w, 0.f);
    float* row = out + (size_t)d * FOUT + c0;
    *(float4*)row       = r0;
    *(float4*)(row + 4) = r1;
}

// ---------------- launch ------------------------------------------------------
extern "C" void kernel_launch(void* const* d_in, const int* in_sizes, int n_in,
                              void* d_out, int out_size) {
    const float* x       = (const float*)d_in[0];
    const void*  eidx    = d_in[1];
    const float* W       = (const float*)d_in[2];
    const float* att_src = (const float*)d_in[3];
    const float* att_dst = (const float*)d_in[4];
    const float* bias    = (const float*)d_in[5];
    const float* gamma   = (const float*)d_in[6];
    const float* beta    = (const float*)d_in[7];
    float* out = (float*)d_out;

    const int n = in_sizes[0] / FIN;     // 50000
    const int e = in_sizes[1] / 2;       // 800000

    int cnt = 64 < 2 * e ? 64 : 2 * e;
    detect_idx_kernel<<<1, 32>>>((const long long*)eidx, n, cnt);

    wz_kernel<<<(FOUT * FIN + 255) / 256, 256>>>(W, n);

    dim3 ggrid((n + 127) / 128, FOUT / 128);
    gemm_mma_kernel<<<ggrid, 256>>>(x, att_src, att_dst, n);

    const int nb = (n + 255) / 256;      // 196
    count_kernel<<<(e + 255) / 256, 256>>>(eidx, e);
    scan1_kernel<<<nb, 256>>>(n);
    scan2_kernel<<<1, 256>>>(nb, n);
    scan3_kernel<<<nb, 256>>>(n);
    fill_kernel<<<(e + 255) / 256, 256>>>(eidx, e);

    aggregate_kernel<<<(n * 32 + 255) / 256, 256>>>(out, bias, gamma, beta, n);
}

// round 14
// speedup vs baseline: 7.0625x; 1.1196x over previous
#include <cuda_runtime.h>
#include <cuda_bf16.h>
#include <cuda_fp16.h>
#include <cstdint>

#define NNODES 50000
#define NEDGES 800000
#define FIN 256
#define FOUT 256
#define HEADS 8
#define CH 32
#define NEG_SLOPE 0.2f
#define LN_EPS 1e-5f

// ---------------- scratch (static device globals) -----------------------------
__device__ __half g_hf[(size_t)NNODES * FOUT];   // h in fp16, 25.6 MB
__device__ __nv_bfloat16 g_wh[FOUT * FIN];       // Wt hi: [n][k]
__device__ __nv_bfloat16 g_wl[FOUT * FIN];       // Wt lo: [n][k]
__device__ float g_asrc[NNODES * HEADS];
__device__ float g_adst[NNODES * HEADS];
__device__ int   g_cnt[NNODES];
__device__ int   g_off[NNODES + 1];
__device__ int   g_cur[NNODES];
__device__ int   g_col[NEDGES];
__device__ int   g_bsum[256];
__device__ int   g_is64;

__device__ __forceinline__ float leaky(float v) {
    return v > 0.f ? v : NEG_SLOPE * v;
}

__device__ __forceinline__ uint32_t smem_u32(const void* p) {
    uint32_t a;
    asm("{ .reg .u64 t; cvta.to.shared.u64 t, %1; cvt.u32.u64 %0, t; }"
        : "=r"(a) : "l"(p));
    return a;
}

// ---------------- int64/int32 edge-index detection ----------------------------
__global__ void detect_idx_kernel(const long long* __restrict__ ei, int n, int cnt) {
    if (threadIdx.x == 0 && blockIdx.x == 0) {
        int ok = 1;
        for (int i = 0; i < cnt; ++i) {
            long long v = ei[i];
            if (v < 0 || v >= (long long)n) { ok = 0; break; }
        }
        g_is64 = ok;
    }
}

__device__ __forceinline__ void load_edge(const void* eidx, int e, int i,
                                          int& src, int& dst) {
    if (g_is64) {
        const long long* p = (const long long*)eidx;
        src = (int)p[i];
        dst = (int)p[(size_t)e + i];
    } else {
        const int* p = (const int*)eidx;
        src = p[i];
        dst = p[e + i];
    }
}

// ---------------- W conversion: fp32 -> bf16 hi/lo transposed -----------------
__global__ void wconv_kernel(const float* __restrict__ W) {
    int idx = blockIdx.x * blockDim.x + threadIdx.x;
    if (idx < FOUT * FIN) {
        int nn = idx >> 8;     // out channel
        int k = idx & 255;     // in channel
        float w = W[k * FOUT + nn];
        __nv_bfloat16 hi = __float2bfloat16(w);
        __nv_bfloat16 lo = __float2bfloat16(w - __bfloat162float(hi));
        g_wh[nn * FIN + k] = hi;
        g_wl[nn * FIN + k] = lo;
    }
}

__global__ void zero_cnt_kernel(int n) {
    int i = blockIdx.x * blockDim.x + threadIdx.x;
    if (i < n) g_cnt[i] = 0;
}

// pack 8 fp32 -> uint4 of 8 bf16 (hi part, or residual-lo part)
__device__ __forceinline__ uint4 cvt8_bf16(float4 v0, float4 v1, bool lo) {
    float f[8] = {v0.x, v0.y, v0.z, v0.w, v1.x, v1.y, v1.z, v1.w};
    unsigned r[4];
#pragma unroll
    for (int i = 0; i < 4; ++i) {
        float fa = f[2 * i], fb = f[2 * i + 1];
        __nv_bfloat16 ha = __float2bfloat16(fa);
        __nv_bfloat16 hb = __float2bfloat16(fb);
        if (lo) {
            ha = __float2bfloat16(fa - __bfloat162float(ha));
            hb = __float2bfloat16(fb - __bfloat162float(hb));
        }
        __nv_bfloat162 t = __nv_bfloat162(ha, hb);
        r[i] = *reinterpret_cast<unsigned*>(&t);
    }
    return make_uint4(r[0], r[1], r[2], r[3]);
}

// ---------------- K1: double-buffered bf16 mma GEMM + fused conv + logits ------
// h = xh@Wh + xl@Wh + xh@Wl ; CTA 128x128; h stored fp16;
// per-head att logits fused in epilogue
#define APITCH 40
#define NITER 24
__global__ __launch_bounds__(256) void gemm_mma_kernel(const float* __restrict__ x,
                                                       const float* __restrict__ att_src,
                                                       const float* __restrict__ att_dst,
                                                       int M) {
    __shared__ __nv_bfloat16 As[2][128][APITCH];
    __shared__ __nv_bfloat16 Bs[2][128][APITCH];

    const int tid = threadIdx.x;
    const int warp = tid >> 5;
    const int lane = tid & 31;
    const int wm = warp & 1;
    const int wn = warp >> 1;
    const int m0 = blockIdx.x * 128;
    const int n0 = blockIdx.y * 128;

    float acc[4][4][4];
#pragma unroll
    for (int a = 0; a < 4; ++a)
#pragma unroll
        for (int b = 0; b < 4; ++b)
#pragma unroll
            for (int c = 0; c < 4; ++c) acc[a][b][c] = 0.f;

    const int lrow = tid >> 1;            // 0..127
    const int lk = (tid & 1) * 16;        // 0 or 16

    const int arow = wm * 64 + (lane & 7) + ((lane >> 3) & 1) * 8;
    const int acol = (lane >> 4) * 8;
    const int l16 = lane & 15;
    const int brow = wn * 32 + (l16 & 7);
    const int bcol = ((l16 >> 3) & 1) * 8;

    const int gr = m0 + lrow;
    const bool rok = gr < M;

    // it in [0,24): term t=it/8 (0: xh*Wh, 1: xl*Wh, 2: xh*Wl), kchunk=(it%8)*32
    auto load_tiles = [&](int it, uint4& a0, uint4& a1, uint4& b0, uint4& b1) {
        const int t = it >> 3;
        const int kc = (it & 7) << 5;
        const bool alo = (t == 1);
        const __nv_bfloat16* Bg = (t == 2) ? g_wl : g_wh;
        if (rok) {
            const float* ap = x + (size_t)gr * FIN + kc + lk;
            float4 v0 = __ldg((const float4*)ap);
            float4 v1 = __ldg((const float4*)(ap + 4));
            float4 v2 = __ldg((const float4*)(ap + 8));
            float4 v3 = __ldg((const float4*)(ap + 12));
            a0 = cvt8_bf16(v0, v1, alo);
            a1 = cvt8_bf16(v2, v3, alo);
        } else {
            a0 = make_uint4(0, 0, 0, 0);
            a1 = make_uint4(0, 0, 0, 0);
        }
        const __nv_bfloat16* bp = Bg + (size_t)(n0 + lrow) * FIN + kc + lk;
        b0 = *(const uint4*)bp;
        b1 = *(const uint4*)(bp + 8);
    };

    {
        uint4 a0, a1, b0, b1;
        load_tiles(0, a0, a1, b0, b1);
        *(uint4*)&As[0][lrow][lk]     = a0;
        *(uint4*)&As[0][lrow][lk + 8] = a1;
        *(uint4*)&Bs[0][lrow][lk]     = b0;
        *(uint4*)&Bs[0][lrow][lk + 8] = b1;
    }
    __syncthreads();

    for (int it = 0; it < NITER; ++it) {
        const int cur = it & 1;
        const int nxt = cur ^ 1;
        const bool more = (it + 1 < NITER);
        uint4 pa0, pa1, pb0, pb1;
        if (more) load_tiles(it + 1, pa0, pa1, pb0, pb1);

#pragma unroll
        for (int ks = 0; ks < 32; ks += 16) {
            uint32_t a[4][4];
#pragma unroll
            for (int mf = 0; mf < 4; ++mf) {
                uint32_t ad = smem_u32(&As[cur][arow + mf * 16][ks + acol]);
                asm volatile(
                    "ldmatrix.sync.aligned.m8n8.x4.shared.b16 {%0,%1,%2,%3}, [%4];"
                    : "=r"(a[mf][0]), "=r"(a[mf][1]), "=r"(a[mf][2]), "=r"(a[mf][3])
                    : "r"(ad));
            }
            uint32_t b[4][2];
#pragma unroll
            for (int nf = 0; nf < 4; ++nf) {
                uint32_t bd = smem_u32(&Bs[cur][brow + nf * 8][ks + bcol]);
                asm volatile(
                    "ldmatrix.sync.aligned.m8n8.x2.shared.b16 {%0,%1}, [%2];"
                    : "=r"(b[nf][0]), "=r"(b[nf][1]) : "r"(bd));
            }
#pragma unroll
            for (int mf = 0; mf < 4; ++mf)
#pragma unroll
                for (int nf = 0; nf < 4; ++nf) {
                    asm volatile(
                        "mma.sync.aligned.m16n8k16.row.col.f32.bf16.bf16.f32 "
                        "{%0,%1,%2,%3}, {%4,%5,%6,%7}, {%8,%9}, {%0,%1,%2,%3};"
                        : "+f"(acc[mf][nf][0]), "+f"(acc[mf][nf][1]),
                          "+f"(acc[mf][nf][2]), "+f"(acc[mf][nf][3])
                        : "r"(a[mf][0]), "r"(a[mf][1]), "r"(a[mf][2]), "r"(a[mf][3]),
                          "r"(b[nf][0]), "r"(b[nf][1]));
                }
        }

        if (more) {
            *(uint4*)&As[nxt][lrow][lk]     = pa0;
            *(uint4*)&As[nxt][lrow][lk + 8] = pa1;
            *(uint4*)&Bs[nxt][lrow][lk]     = pb0;
            *(uint4*)&Bs[nxt][lrow][lk + 8] = pb1;
        }
        __syncthreads();
    }

    // ---- epilogue: store h (fp16) + fused per-head attention logits ----
    const int rbase = m0 + wm * 64 + (lane >> 2);
    const int cbase = n0 + wn * 32 + (lane & 3) * 2;
    const int head = (n0 >> 5) + wn;   // warp's 32-col span = exactly one head

    float asv[8], adv[8];
#pragma unroll
    for (int nf = 0; nf < 4; ++nf)
#pragma unroll
        for (int t = 0; t < 2; ++t) {
            int c = (lane & 3) * 2 + nf * 8 + t;
            asv[nf * 2 + t] = __ldg(att_src + head * CH + c);
            adv[nf * 2 + t] = __ldg(att_dst + head * CH + c);
        }

#pragma unroll
    for (int mf = 0; mf < 4; ++mf) {
#pragma unroll
        for (int sub = 0; sub < 2; ++sub) {
            int r = rbase + mf * 16 + sub * 8;
            float ds = 0.f, dd = 0.f;
#pragma unroll
            for (int nf = 0; nf < 4; ++nf) {
                float v0 = acc[mf][nf][sub * 2 + 0];
                float v1 = acc[mf][nf][sub * 2 + 1];
                if (r < M) {
                    __half2 hv = __floats2half2_rn(v0, v1);
                    *(__half2*)(g_hf + (size_t)r * FOUT + cbase + nf * 8) = hv;
                }
                ds += v0 * asv[nf * 2] + v1 * asv[nf * 2 + 1];
                dd += v0 * adv[nf * 2] + v1 * adv[nf * 2 + 1];
            }
            ds += __shfl_xor_sync(0xffffffffu, ds, 1);
            ds += __shfl_xor_sync(0xffffffffu, ds, 2);
            dd += __shfl_xor_sync(0xffffffffu, dd, 1);
            dd += __shfl_xor_sync(0xffffffffu, dd, 2);
            if ((lane & 3) == 0 && r < M) {
                g_asrc[r * HEADS + head] = ds;
                g_adst[r * HEADS + head] = dd;
            }
        }
    }
}

// ---------------- CSR build ----------------------------------------------------
__global__ void count_kernel(const void* __restrict__ eidx, int e) {
    int i = blockIdx.x * blockDim.x + threadIdx.x;
    if (i >= e) return;
    int dst;
    if (g_is64) dst = (int)((const long long*)eidx)[(size_t)e + i];
    else        dst = ((const int*)eidx)[e + i];
    atomicAdd(&g_cnt[dst], 1);
}

__global__ __launch_bounds__(256) void scan1_kernel(int n) {
    __shared__ int sh[256];
    int i = blockIdx.x * 256 + threadIdx.x;
    sh[threadIdx.x] = (i < n) ? g_cnt[i] : 0;
    __syncthreads();
    for (int o = 128; o; o >>= 1) {
        if (threadIdx.x < o) sh[threadIdx.x] += sh[threadIdx.x + o];
        __syncthreads();
    }
    if (threadIdx.x == 0) g_bsum[blockIdx.x] = sh[0];
}

__global__ __launch_bounds__(256) void scan2_kernel(int nb, int n) {
    __shared__ int sh[256];
    int t = threadIdx.x;
    sh[t] = (t < nb) ? g_bsum[t] : 0;
    __syncthreads();
    for (int o = 1; o < 256; o <<= 1) {
        int v = (t >= o) ? sh[t - o] : 0;
        __syncthreads();
        sh[t] += v;
        __syncthreads();
    }
    if (t < nb) g_bsum[t] = sh[t];       // inclusive
    if (t == 255) g_off[n] = sh[nb - 1];
}

__global__ __launch_bounds__(256) void scan3_kernel(int n) {
    __shared__ int sh[256];
    int t = threadIdx.x;
    int i = blockIdx.x * 256 + t;
    int v = (i < n) ? g_cnt[i] : 0;
    sh[t] = v;
    __syncthreads();
    for (int o = 1; o < 256; o <<= 1) {
        int u = (t >= o) ? sh[t - o] : 0;
        __syncthreads();
        sh[t] += u;
        __syncthreads();
    }
    int bex = (blockIdx.x > 0) ? g_bsum[blockIdx.x - 1] : 0;
    if (i < n) {
        int off = bex + sh[t] - v;   // exclusive
        g_off[i] = off;
        g_cur[i] = off;
    }
}

__global__ void fill_kernel(const void* __restrict__ eidx, int e) {
    int i = blockIdx.x * blockDim.x + threadIdx.x;
    if (i >= e) return;
    int src, dst;
    load_edge(eidx, e, i, src, dst);
    int pos = atomicAdd(&g_cur[dst], 1);
    g_col[pos] = src;
}

// unpack 8 fp16 -> two float4
__device__ __forceinline__ void h8_to_f(uint4 hv, float4& f0, float4& f1) {
    const __half2* hp = (const __half2*)&hv;
    float2 a = __half22float2(hp[0]);
    float2 b = __half22float2(hp[1]);
    float2 c = __half22float2(hp[2]);
    float2 d = __half22float2(hp[3]);
    f0 = make_float4(a.x, a.y, b.x, b.y);
    f1 = make_float4(c.x, c.y, d.x, d.y);
}

// accumulate one edge: fetch weight for my head, fma 8 channels
__device__ __forceinline__ void acc_edge(float wgt, uint4 hv, int myhead,
                                         float4& acc0, float4& acc1) {
    float av = __shfl_sync(0xffffffffu, wgt, myhead);
    float4 f0, f1;
    h8_to_f(hv, f0, f1);
    acc0.x += f0.x * av; acc0.y += f0.y * av;
    acc0.z += f0.z * av; acc0.w += f0.w * av;
    acc1.x += f1.x * av; acc1.y += f1.y * av;
    acc1.z += f1.z * av; acc1.w += f1.w * av;
}

// -------- single-pass aggregate: unnormalized numerator + denominator fused ---
__global__ __launch_bounds__(256) void aggregate_kernel(float* __restrict__ out,
                                                        const float* __restrict__ bias,
                                                        const float* __restrict__ gamma,
                                                        const float* __restrict__ beta,
                                                        int n) {
    int d = (blockIdx.x * blockDim.x + threadIdx.x) >> 5;
    int lane = threadIdx.x & 31;
    if (d >= n) return;

    const int off = g_off[d];
    const int deg = g_off[d + 1] - off;

    float4 t0 = *(const float4*)(g_adst + d * HEADS);
    float4 t1 = *(const float4*)(g_adst + d * HEADS + 4);
    float adst8[8] = {t0.x, t0.y, t0.z, t0.w, t1.x, t1.y, t1.z, t1.w};
    float4 u0 = *(const float4*)(g_asrc + d * HEADS);
    float4 u1 = *(const float4*)(g_asrc + d * HEADS + 4);
    float asd[8] = {u0.x, u0.y, u0.z, u0.w, u1.x, u1.y, u1.z, u1.w};

    const int lk = lane & 7;        // head this lane evaluates weights for
    const int myhead = lane >> 2;   // head owning this lane's 8 output channels
    float adst_lk = 0.f, asd_lk = 0.f;
#pragma unroll
    for (int k = 0; k < 8; ++k)
        if (lk == k) { adst_lk = adst8[k]; asd_lk = asd[k]; }

    // self-loop: weight for head lk; numerator seeded with myhead's self weight
    float sw = __expf(leaky(asd_lk + adst_lk));
    float ws_my = __shfl_sync(0xffffffffu, sw, myhead);

    uint4 shv = __ldg((const uint4*)(g_hf + (size_t)d * FOUT + lane * 8));
    float4 v0, v1;
    h8_to_f(shv, v0, v1);
    float4 acc0 = make_float4(v0.x * ws_my, v0.y * ws_my, v0.z * ws_my, v0.w * ws_my);
    float4 acc1 = make_float4(v1.x * ws_my, v1.y * ws_my, v1.z * ws_my, v1.w * ws_my);

    int j = 0;
    for (; j + 4 <= deg; j += 4) {
        int s0 = __ldg(g_col + off + j);
        int s1 = __ldg(g_col + off + j + 1);
        int s2 = __ldg(g_col + off + j + 2);
        int s3 = __ldg(g_col + off + j + 3);
        float a0 = __ldg(g_asrc + s0 * HEADS + lk);
        float a1 = __ldg(g_asrc + s1 * HEADS + lk);
        float a2 = __ldg(g_asrc + s2 * HEADS + lk);
        float a3 = __ldg(g_asrc + s3 * HEADS + lk);
        uint4 hv0 = __ldg((const uint4*)(g_hf + (size_t)s0 * FOUT + lane * 8));
        uint4 hv1 = __ldg((const uint4*)(g_hf + (size_t)s1 * FOUT + lane * 8));
        uint4 hv2 = __ldg((const uint4*)(g_hf + (size_t)s2 * FOUT + lane * 8));
        uint4 hv3 = __ldg((const uint4*)(g_hf + (size_t)s3 * FOUT + lane * 8));
        float w0 = __expf(leaky(a0 + adst_lk));
        float w1 = __expf(leaky(a1 + adst_lk));
        float w2 = __expf(leaky(a2 + adst_lk));
        float w3 = __expf(leaky(a3 + adst_lk));
        sw += w0 + w1 + w2 + w3;
        acc_edge(w0, hv0, myhead, acc0, acc1);
        acc_edge(w1, hv1, myhead, acc0, acc1);
        acc_edge(w2, hv2, myhead, acc0, acc1);
        acc_edge(w3, hv3, myhead, acc0, acc1);
    }
    for (; j < deg; ++j) {
        int s0 = __ldg(g_col + off + j);
        float a0 = __ldg(g_asrc + s0 * HEADS + lk);
        uint4 hv0 = __ldg((const uint4*)(g_hf + (size_t)s0 * FOUT + lane * 8));
        float w0 = __expf(leaky(a0 + adst_lk));
        sw += w0;
        acc_edge(w0, hv0, myhead, acc0, acc1);
    }

    // normalize by my head's denominator
    float dsum = __shfl_sync(0xffffffffu, sw, myhead);
    float rin = 1.f / dsum;
    acc0.x *= rin; acc0.y *= rin; acc0.z *= rin; acc0.w *= rin;
    acc1.x *= rin; acc1.y *= rin; acc1.z *= rin; acc1.w *= rin;

    // ---- bias + LayerNorm + ReLU ----
    const int c0 = lane * 8;
    float4 b0 = *(const float4*)(bias + c0);
    float4 b1 = *(const float4*)(bias + c0 + 4);
    acc0.x += b0.x; acc0.y += b0.y; acc0.z += b0.z; acc0.w += b0.w;
    acc1.x += b1.x; acc1.y += b1.y; acc1.z += b1.z; acc1.w += b1.w;

    float s = acc0.x + acc0.y + acc0.z + acc0.w + acc1.x + acc1.y + acc1.z + acc1.w;
    float q = acc0.x * acc0.x + acc0.y * acc0.y + acc0.z * acc0.z + acc0.w * acc0.w +
              acc1.x * acc1.x + acc1.y * acc1.y + acc1.z * acc1.z + acc1.w * acc1.w;
#pragma unroll
    for (int o = 16; o; o >>= 1) {
        s += __shfl_xor_sync(0xffffffffu, s, o);
        q += __shfl_xor_sync(0xffffffffu, q, o);
    }
    float mu = s * (1.f / FOUT);
    float var = q * (1.f / FOUT) - mu * mu;
    float rs = rsqrtf(var + LN_EPS);

    float4 g0 = *(const float4*)(gamma + c0);
    float4 g1 = *(const float4*)(gamma + c0 + 4);
    float4 e0 = *(const float4*)(beta + c0);
    float4 e1 = *(const float4*)(beta + c0 + 4);
    float4 r0, r1;
    r0.x = fmaxf((acc0.x - mu) * rs * g0.x + e0.x, 0.f);
    r0.y = fmaxf((acc0.y - mu) * rs * g0.y + e0.y, 0.f);
    r0.z = fmaxf((acc0.z - mu) * rs * g0.z + e0.z, 0.f);
    r0.w = fmaxf((acc0.w - mu) * rs * g0.w + e0.w, 0.f);
    r1.x = fmaxf((acc1.x - mu) * rs * g1.x + e1.x, 0.f);
    r1.y = fmaxf((acc1.y - mu) * rs * g1.y + e1.y, 0.f);
    r1.z = fmaxf((acc1.z - mu) * rs * g1.z + e1.z, 0.f);
    r1.w = fmaxf((acc1.w - mu) * rs * g1.w + e1.w, 0.f);
    float* row = out + (size_t)d * FOUT + c0;
    *(float4*)row       = r0;
    *(float4*)(row + 4) = r1;
}

// ---------------- launch: fork CSR chain onto side stream ---------------------
extern "C" void kernel_launch(void* const* d_in, const int* in_sizes, int n_in,
                              void* d_out, int out_size) {
    const float* x       = (const float*)d_in[0];
    const void*  eidx    = d_in[1];
    const float* W       = (const float*)d_in[2];
    const float* att_src = (const float*)d_in[3];
    const float* att_dst = (const float*)d_in[4];
    const float* bias    = (const float*)d_in[5];
    const float* gamma   = (const float*)d_in[6];
    const float* beta    = (const float*)d_in[7];
    float* out = (float*)d_out;

    const int n = in_sizes[0] / FIN;     // 50000
    const int e = in_sizes[1] / 2;       // 800000

    // lazily created on first (non-captured) call; reused by capture
    static cudaStream_t s2 = nullptr;
    static cudaEvent_t evF = nullptr, evJ = nullptr;
    if (s2 == nullptr) {
        cudaStreamCreateWithFlags(&s2, cudaStreamNonBlocking);
        cudaEventCreateWithFlags(&evF, cudaEventDisableTiming);
        cudaEventCreateWithFlags(&evJ, cudaEventDisableTiming);
    }

    int cnt = 64 < 2 * e ? 64 : 2 * e;
    detect_idx_kernel<<<1, 32>>>((const long long*)eidx, n, cnt);

    // fork: CSR chain on s2 (depends only on eidx + g_is64)
    cudaEventRecord(evF, 0);
    cudaStreamWaitEvent(s2, evF, 0);

    const int nb = (n + 255) / 256;      // 196
    zero_cnt_kernel<<<nb, 256, 0, s2>>>(n);
    count_kernel<<<(e + 255) / 256, 256, 0, s2>>>(eidx, e);
    scan1_kernel<<<nb, 256, 0, s2>>>(n);
    scan2_kernel<<<1, 256, 0, s2>>>(nb, n);
    scan3_kernel<<<nb, 256, 0, s2>>>(n);
    fill_kernel<<<(e + 255) / 256, 256, 0, s2>>>(eidx, e);
    cudaEventRecord(evJ, s2);

    // main stream: W conversion + GEMM (independent of CSR)
    wconv_kernel<<<(FOUT * FIN + 255) / 256, 256>>>(W);
    dim3 ggrid((n + 127) / 128, FOUT / 128);
    gemm_mma_kernel<<<ggrid, 256>>>(x, att_src, att_dst, n);

    // join, then aggregate (needs h/asrc/adst AND CSR)
    cudaStreamWaitEvent(0, evJ, 0);
    aggregate_kernel<<<(n * 32 + 255) / 256, 256>>>(out, bias, gamma, beta, n);
}